// round 1
// baseline (speedup 1.0000x reference)
#include <cuda_runtime.h>
#include <math.h>

#define BB 4
#define DD 96
#define HH 160
#define WW 160
#define TX 32
#define TY 8
#define NSCAL 28
#define NACC  78   // 28 scalars + 50 histogram bins

// Global accumulators (double) — zeroed every launch by zero_kernel.
__device__ double g_acc[BB][NACC];
// Derived separable gabor weights: u[f][j] (9 yx taps) and c[f] (box term).
__device__ float g_u[72];
__device__ float g_cf[8];

__global__ void zero_kernel() {
    int i = blockIdx.x * blockDim.x + threadIdx.x;
    if (i < BB * NACC) ((double*)g_acc)[i] = 0.0;
}

// Derive separable decomposition from the input gabor filters:
// F[dz][j] = gz[dz]*u[j] - c  with gz = [a,1,a], a = exp(-2).
// => u[j] = (F[1][j]-F[0][j])/(1-a),  c = mean_j(u[j]-F[1][j])
__global__ void prep_kernel(const float* __restrict__ gf) {
    int f = threadIdx.x;
    if (f < 8) {
        const float A = 0.13533528323661270f;  // exp(-2)
        float cacc = 0.0f;
        #pragma unroll
        for (int j = 0; j < 9; j++) {
            float F1 = gf[f * 27 + 9 + j];
            float F0 = gf[f * 27 + j];
            float uj = (F1 - F0) * (1.0f / (1.0f - A));
            g_u[f * 9 + j] = uj;
            cacc += (uj - F1);
        }
        g_cf[f] = cacc * (1.0f / 9.0f);
    }
}

__global__ __launch_bounds__(TX * TY)
void main_kernel(const float* __restrict__ X, const float* __restrict__ M) {
    __shared__ float xs[3][TY + 2][TX + 2];
    __shared__ float ms[3][TY + 2][TX + 2];
    __shared__ float shHist[50];
    __shared__ float partial[NSCAL][8];

    const int tx = threadIdx.x, ty = threadIdx.y;
    const int tid = ty * TX + tx;
    const int bx = blockIdx.x, by = blockIdx.y, b = blockIdx.z;
    const int x0 = bx * TX, y0 = by * TY;

    if (tid < 50) shHist[tid] = 0.0f;

    const float* Xb = X + (size_t)b * DD * HH * WW;
    const float* Mb = M + (size_t)b * DD * HH * WW;

    // Load derived gabor weights into registers (warp-uniform).
    float u[8][9], cf[8];
    #pragma unroll
    for (int f = 0; f < 8; f++) {
        cf[f] = g_cf[f];
        #pragma unroll
        for (int j = 0; j < 9; j++) u[f][j] = g_u[f * 9 + j];
    }

    auto loadPlane = [&](int zz, int s) {
        for (int i = tid; i < (TY + 2) * (TX + 2); i += TX * TY) {
            int ry = i / (TX + 2), rx = i % (TX + 2);
            int gy = y0 + ry - 1, gx = x0 + rx - 1;
            float xv = 0.0f, mv = 0.0f;
            if (zz >= 0 && zz < DD && gy >= 0 && gy < HH && gx >= 0 && gx < WW) {
                size_t off = (size_t)zz * HH * WW + (size_t)gy * WW + gx;
                xv = __ldg(Xb + off);
                mv = __ldg(Mb + off);
            }
            (&xs[s][0][0])[i] = xv;
            (&ms[s][0][0])[i] = mv;
        }
    };

    // Preload: slot(zz) = ((zz % 3)+3)%3 → plane -1 in slot 2 (zeros), 0 in 0, 1 in 1.
    loadPlane(0, 0);
    loadPlane(1, 1);
    for (int i = tid; i < (TY + 2) * (TX + 2); i += TX * TY) {
        (&xs[2][0][0])[i] = 0.0f;
        (&ms[2][0][0])[i] = 0.0f;
    }

    float n = 0, s1 = 0, s2 = 0, s3 = 0, s4 = 0;
    float gab[8] = {0, 0, 0, 0, 0, 0, 0, 0};
    float lbp[6] = {0, 0, 0, 0, 0, 0};
    float gsv[3] = {0, 0, 0}, gcv[3] = {0, 0, 0}, ghv[3] = {0, 0, 0};
    const float A = 0.13533528323661270f;

    for (int z = 0; z < DD; z++) {
        __syncthreads();
        const int sm1 = (z + 2) % 3, sc = z % 3, sp1 = (z + 1) % 3;

        float c  = xs[sc][ty + 1][tx + 1];
        float mc = ms[sc][ty + 1][tx + 1];

        // ---- masked raw moments ----
        float c2 = c * c;
        n += mc;
        s1 = fmaf(mc, c, s1);
        s2 = fmaf(mc, c2, s2);
        float mcc = mc * c;
        s3 = fmaf(mcc, c2, s3);
        s4 = fmaf(mc * c2, c2, s4);

        // ---- histogram (w = mf * [v in [-1,1]]) ----
        if (mc > 0.5f && c >= -1.0f && c <= 1.0f) {
            int bi = (int)floorf(__fmul_rn(__fadd_rn(c, 1.0f), 25.0f));
            bi = min(max(bi, 0), 49);
            atomicAdd(&shHist[bi], 1.0f);
        }

        // ---- gabor: conv_f = sum_j u[f][j]*tz_j - c_f*box27 ----
        float box = 0.0f;
        float g[8] = {0, 0, 0, 0, 0, 0, 0, 0};
        #pragma unroll
        for (int dy = 0; dy < 3; dy++) {
            #pragma unroll
            for (int dx = 0; dx < 3; dx++) {
                float xm = xs[sm1][ty + dy][tx + dx];
                float xc = xs[sc ][ty + dy][tx + dx];
                float xp = xs[sp1][ty + dy][tx + dx];
                float mp2 = xm + xp;
                float tz  = fmaf(A, mp2, xc);
                box += mp2 + xc;
                const int j = dy * 3 + dx;
                #pragma unroll
                for (int f = 0; f < 8; f++) g[f] = fmaf(u[f][j], tz, g[f]);
            }
        }
        #pragma unroll
        for (int f = 0; f < 8; f++) {
            float gv = fmaf(-cf[f], box, g[f]);
            gab[f] = fmaf(fabsf(gv), mc, gab[f]);
        }

        // ---- neighbors for LBP / GLCM (exact float diffs) ----
        float xup = xs[sp1][ty + 1][tx + 1];
        float xdn = xs[sm1][ty + 1][tx + 1];
        float xyp = xs[sc][ty + 2][tx + 1];
        float xym = xs[sc][ty    ][tx + 1];
        float xxp = xs[sc][ty + 1][tx + 2];
        float xxm = xs[sc][ty + 1][tx    ];

        if (mc > 0.5f) {
            lbp[0] += (c - xup > 0.0f) ? 1.0f : 0.0f;  // axis D, +1
            lbp[1] += (c - xdn > 0.0f) ? 1.0f : 0.0f;  // axis D, -1
            lbp[2] += (c - xyp > 0.0f) ? 1.0f : 0.0f;  // axis H, +1
            lbp[3] += (c - xym > 0.0f) ? 1.0f : 0.0f;  // axis H, -1
            lbp[4] += (c - xxp > 0.0f) ? 1.0f : 0.0f;  // axis W, +1
            lbp[5] += (c - xxm > 0.0f) ? 1.0f : 0.0f;  // axis W, -1
        }

        // ---- GLCM proxy (halo zeros make boundary pairs vanish automatically) ----
        float mzp = ms[sp1][ty + 1][tx + 1];
        float myp = ms[sc][ty + 2][tx + 1];
        float mxp = ms[sc][ty + 1][tx + 2];
        {
            float mp = (mc > 0.5f && mzp > 0.5f) ? 1.0f : 0.0f;
            float d = c - xup; float dd = d * d;
            gsv[0] += mp;
            gcv[0] = fmaf(mp, dd, gcv[0]);
            ghv[0] = fmaf(mp, __fdividef(1.0f, 1.0f + dd), ghv[0]);
        }
        {
            float mp = (mc > 0.5f && myp > 0.5f) ? 1.0f : 0.0f;
            float d = c - xyp; float dd = d * d;
            gsv[1] += mp;
            gcv[1] = fmaf(mp, dd, gcv[1]);
            ghv[1] = fmaf(mp, __fdividef(1.0f, 1.0f + dd), ghv[1]);
        }
        {
            float mp = (mc > 0.5f && mxp > 0.5f) ? 1.0f : 0.0f;
            float d = c - xxp; float dd = d * d;
            gsv[2] += mp;
            gcv[2] = fmaf(mp, dd, gcv[2]);
            ghv[2] = fmaf(mp, __fdividef(1.0f, 1.0f + dd), ghv[2]);
        }

        __syncthreads();
        loadPlane(z + 2, (z + 2) % 3);
    }

    // ---- block reduction: 28 scalars via warp shuffles, then double atomics ----
    float vals[NSCAL];
    vals[0] = n; vals[1] = s1; vals[2] = s2; vals[3] = s3; vals[4] = s4;
    #pragma unroll
    for (int f = 0; f < 8; f++) vals[5 + f] = gab[f];
    #pragma unroll
    for (int k = 0; k < 6; k++) vals[13 + k] = lbp[k];
    #pragma unroll
    for (int a = 0; a < 3; a++) {
        vals[19 + 3 * a] = gsv[a];
        vals[20 + 3 * a] = gcv[a];
        vals[21 + 3 * a] = ghv[a];
    }

    int lane = tid & 31, warp = tid >> 5;
    #pragma unroll
    for (int k = 0; k < NSCAL; k++) {
        float v = vals[k];
        #pragma unroll
        for (int o = 16; o > 0; o >>= 1) v += __shfl_down_sync(0xffffffffu, v, o);
        if (lane == 0) partial[k][warp] = v;
    }
    __syncthreads();  // also orders shHist shared atomics

    if (tid < NSCAL) {
        double acc = 0.0;
        #pragma unroll
        for (int w = 0; w < 8; w++) acc += (double)partial[tid][w];
        atomicAdd(&g_acc[b][tid], acc);
    }
    if (tid >= 64 && tid < 114) {
        int hb = tid - 64;
        atomicAdd(&g_acc[b][NSCAL + hb], (double)shHist[hb]);
    }
}

__global__ void finalize_kernel(float* __restrict__ out) {
    int b = threadIdx.x;
    if (b >= BB) return;
    const double* a = g_acc[b];
    double n = a[0];
    double nn = n > 1.0 ? n : 1.0;
    double mu = a[1] / nn;
    double M2 = a[2] - 2.0 * mu * a[1] + mu * mu * n;
    double nm1 = (n - 1.0) > 1.0 ? (n - 1.0) : 1.0;
    double var = M2 / nm1;
    double sigma = sqrt(var) + 1e-8;
    double M3 = a[3] - 3.0 * mu * a[2] + 3.0 * mu * mu * a[1] - mu * mu * mu * n;
    double M4 = a[4] - 4.0 * mu * a[3] + 6.0 * mu * mu * a[2]
              - 4.0 * mu * mu * mu * a[1] + mu * mu * mu * mu * n;
    double sg3 = sigma * sigma * sigma;
    double skew = (M3 / sg3) / nn;
    double kurt = (M4 / (sg3 * sigma)) / nn - 3.0;

    double tot = 0.0;
    for (int k = 0; k < 50; k++) tot += a[NSCAL + k];
    tot += 1e-8;
    double ent = 0.0;
    for (int k = 0; k < 50; k++) {
        double p = a[NSCAL + k] / tot;
        ent -= p * log(p + 1e-8);
    }
    double valid = (n >= 10.0) ? 1.0 : 0.0;

    float* o = out + b * 25;
    o[0] = (float)(mu * valid);
    o[1] = (float)(sigma * valid);
    o[2] = (float)(skew * valid);
    o[3] = (float)(kurt * valid);
    o[4] = (float)(ent * valid);
    for (int f = 0; f < 8; f++) o[5 + f] = (float)(a[5 + f] / nn);
    for (int k = 0; k < 6; k++) o[13 + k] = (float)(a[13 + k] / nn);
    for (int ax = 0; ax < 3; ax++) {
        double s = a[19 + 3 * ax];
        double ss = s > 1.0 ? s : 1.0;
        double ok = (s >= 4.0) ? 1.0 : 0.0;
        o[19 + 2 * ax]     = (float)((a[20 + 3 * ax] / ss) * ok);
        o[19 + 2 * ax + 1] = (float)((a[21 + 3 * ax] / ss) * ok);
    }
}

extern "C" void kernel_launch(void* const* d_in, const int* in_sizes, int n_in,
                              void* d_out, int out_size) {
    const float* x  = (const float*)d_in[0];
    const float* m  = (const float*)d_in[1];
    const float* gf = (const float*)d_in[2];
    // d_in[3] (lbp filters) not needed: structure is fixed (center - neighbor).

    prep_kernel<<<1, 32>>>(gf);
    zero_kernel<<<1, 512>>>();
    dim3 grid(WW / TX, HH / TY, BB);
    dim3 blk(TX, TY);
    main_kernel<<<grid, blk>>>(x, m);
    finalize_kernel<<<1, 32>>>((float*)d_out);
}

// round 2
// speedup vs baseline: 2.2274x; 2.2274x over previous
#include <cuda_runtime.h>
#include <math.h>

#define BB 4
#define DD 96
#define HH 160
#define WW 160
#define HW (HH*WW)
#define NSCAL 28
#define NACC  78   // 28 scalars + 50 histogram bins

// Global accumulators (double) — zeroed every launch by zero_kernel.
__device__ double g_acc[BB][NACC];
// Derived separable gabor weights: u[f][j] (9 yx taps) and c[f] (box term).
__device__ float g_u[72];
__device__ float g_cf[8];

typedef unsigned long long u64t;
__device__ __forceinline__ u64t pack2(float lo, float hi) {
    u64t r; asm("mov.b64 %0,{%1,%2};" : "=l"(r) : "f"(lo), "f"(hi)); return r;
}
__device__ __forceinline__ void unpack2(float& lo, float& hi, u64t v) {
    asm("mov.b64 {%0,%1},%2;" : "=f"(lo), "=f"(hi) : "l"(v));
}
__device__ __forceinline__ void fma2(u64t& d, u64t a, u64t b) {
    asm("fma.rn.f32x2 %0,%1,%2,%0;" : "+l"(d) : "l"(a), "l"(b));
}

__global__ void zero_kernel() {
    int i = blockIdx.x * blockDim.x + threadIdx.x;
    if (i < BB * NACC) ((double*)g_acc)[i] = 0.0;
}

// Derive separable decomposition from the input gabor filters:
// F[dz][j] = gz[dz]*u[j] - c  with gz = [a,1,a], a = exp(-2).
__global__ void prep_kernel(const float* __restrict__ gf) {
    int f = threadIdx.x;
    if (f < 8) {
        const float A = 0.13533528323661270f;  // exp(-2)
        float cacc = 0.0f;
        #pragma unroll
        for (int j = 0; j < 9; j++) {
            float F1 = gf[f * 27 + 9 + j];
            float F0 = gf[f * 27 + j];
            float uj = (F1 - F0) * (1.0f / (1.0f - A));
            g_u[f * 9 + j] = uj;
            cacc += (uj - F1);
        }
        g_cf[f] = cacc * (1.0f / 9.0f);
    }
}

// ============================================================
// Kernel A: gabor features. smem x-tiles, 4-slot ring, 1 sync/z,
// packed f32x2 matvec, mask read directly (coalesced).
// ============================================================
#define ATX 32
#define ATY 4
#define ANL ((ATY + 2) * (ATX + 2))   // 204

__global__ __launch_bounds__(128)
void gabor_kernel(const float* __restrict__ X, const float* __restrict__ M) {
    __shared__ float xs[4][ATY + 2][ATX + 2];
    __shared__ float red[8][4];
    const int tx = threadIdx.x, ty = threadIdx.y;
    const int tid = ty * ATX + tx;
    const int x0 = blockIdx.x * ATX, y0 = blockIdx.y * ATY, b = blockIdx.z;
    const float* Xb = X + (size_t)b * DD * HW;
    const float* Mb = M + (size_t)b * DD * HW;

    // packed weights: pair filters (2p, 2p+1)
    u64t u2[36];
    float cf[8];
    #pragma unroll
    for (int p = 0; p < 4; p++) {
        #pragma unroll
        for (int j = 0; j < 9; j++)
            u2[p * 9 + j] = pack2(g_u[(2 * p) * 9 + j], g_u[(2 * p + 1) * 9 + j]);
    }
    #pragma unroll
    for (int f = 0; f < 8; f++) cf[f] = g_cf[f];

    // precompute halo-load slots (z-invariant)
    int loff[2]; bool lval[2];
    #pragma unroll
    for (int s = 0; s < 2; s++) {
        int i = tid + s * 128;
        bool ok = (i < ANL);
        int ry = i / (ATX + 2), rx = i % (ATX + 2);
        int gy = y0 + ry - 1, gx = x0 + rx - 1;
        lval[s] = ok && gy >= 0 && gy < HH && gx >= 0 && gx < WW;
        loff[s] = gy * WW + gx;
    }

    // preload: plane 0 -> slot0, plane 1 -> slot1, plane -1 (slot3) zeros
    #pragma unroll
    for (int s = 0; s < 2; s++) {
        int i = tid + s * 128;
        if (i < ANL) {
            (&xs[0][0][0])[i] = lval[s] ? __ldg(Xb + loff[s]) : 0.0f;
            (&xs[1][0][0])[i] = lval[s] ? __ldg(Xb + HW + loff[s]) : 0.0f;
            (&xs[3][0][0])[i] = 0.0f;
        }
    }

    const float A = 0.13533528323661270f;
    float gab[8] = {0, 0, 0, 0, 0, 0, 0, 0};
    const int moff = (y0 + ty) * WW + x0 + tx;

    for (int z = 0; z < DD; z++) {
        __syncthreads();
        // stage plane z+2 into registers (overlaps LDG latency with compute)
        float st0 = 0.0f, st1 = 0.0f;
        {
            int zq = z + 2;
            if (zq < DD) {
                const float* P = Xb + (size_t)zq * HW;
                if (lval[0]) st0 = __ldg(P + loff[0]);
                if (lval[1]) st1 = __ldg(P + loff[1]);
            }
        }
        float mc = __ldg(Mb + (size_t)z * HW + moff);

        const int sm1 = (z + 3) & 3, sc = z & 3, sp1 = (z + 1) & 3;
        float box = 0.0f;
        u64t g2[4] = {0ull, 0ull, 0ull, 0ull};
        #pragma unroll
        for (int dy = 0; dy < 3; dy++) {
            #pragma unroll
            for (int dx = 0; dx < 3; dx++) {
                float xm = xs[sm1][ty + dy][tx + dx];
                float xc = xs[sc ][ty + dy][tx + dx];
                float xp = xs[sp1][ty + dy][tx + dx];
                float mp2 = xm + xp;
                float tz = fmaf(A, mp2, xc);
                box += mp2 + xc;
                u64t tzz = pack2(tz, tz);
                const int j = dy * 3 + dx;
                fma2(g2[0], u2[0 * 9 + j], tzz);
                fma2(g2[1], u2[1 * 9 + j], tzz);
                fma2(g2[2], u2[2 * 9 + j], tzz);
                fma2(g2[3], u2[3 * 9 + j], tzz);
            }
        }
        float g[8];
        unpack2(g[0], g[1], g2[0]);
        unpack2(g[2], g[3], g2[1]);
        unpack2(g[4], g[5], g2[2]);
        unpack2(g[6], g[7], g2[3]);
        #pragma unroll
        for (int f = 0; f < 8; f++) {
            float gv = fmaf(-cf[f], box, g[f]);
            gab[f] = fmaf(fabsf(gv), mc, gab[f]);
        }

        // store staged plane into slot (z+2)&3 == (z-2)&3 — not read by compute(z)
        {
            int sw = (z + 2) & 3;
            float* bs = &xs[sw][0][0];
            bs[tid] = st0;                      // tid < 204 always
            if (tid + 128 < ANL) bs[tid + 128] = st1;
        }
    }

    int lane = tid & 31, warp = tid >> 5;
    #pragma unroll
    for (int f = 0; f < 8; f++) {
        float v = gab[f];
        #pragma unroll
        for (int o = 16; o > 0; o >>= 1) v += __shfl_down_sync(0xffffffffu, v, o);
        if (lane == 0) red[f][warp] = v;
    }
    __syncthreads();
    if (tid < 8) {
        double acc = (double)red[tid][0] + (double)red[tid][1]
                   + (double)red[tid][2] + (double)red[tid][3];
        atomicAdd(&g_acc[b][5 + tid], acc);
    }
}

// ============================================================
// Kernel B: moments/hist/lbp/glcm. No smem tiles; z-register
// rotation + coalesced neighbor LDGs (L1/L2 hits).
// ============================================================
__global__ __launch_bounds__(256)
void stats_kernel(const float* __restrict__ X, const float* __restrict__ M) {
    __shared__ float shHist[50];
    __shared__ float red[20][8];
    const int tx = threadIdx.x, ty = threadIdx.y;
    const int tid = ty * 32 + tx;
    const int x = blockIdx.x * 32 + tx, y = blockIdx.y * 8 + ty, b = blockIdx.z;
    if (tid < 50) shHist[tid] = 0.0f;
    __syncthreads();

    const size_t base = (size_t)b * DD * HW + (size_t)y * WW + x;
    const bool xpok = (x + 1 < WW), xmok = (x > 0);
    const bool ypok = (y + 1 < HH), ymok = (y > 0);

    float cprev = 0.0f;
    float c     = __ldg(X + base);
    float mc    = __ldg(M + base);
    float cnext = __ldg(X + base + HW);
    float mnext = __ldg(M + base + HW);

    float n = 0, s1 = 0, s2 = 0, s3 = 0, s4 = 0;
    float lbp[6] = {0, 0, 0, 0, 0, 0};
    float gs[3] = {0, 0, 0}, gc[3] = {0, 0, 0}, gh[3] = {0, 0, 0};

    for (int z = 0; z < DD; z++) {
        size_t o = base + (size_t)z * HW;
        float xyp = ypok ? __ldg(X + o + WW) : 0.0f;
        float xym = ymok ? __ldg(X + o - WW) : 0.0f;
        float xxp = xpok ? __ldg(X + o + 1)  : 0.0f;
        float xxm = xmok ? __ldg(X + o - 1)  : 0.0f;
        float myp = ypok ? __ldg(M + o + WW) : 0.0f;
        float mxp = xpok ? __ldg(M + o + 1)  : 0.0f;

        // moments
        float c2 = c * c;
        n += mc;
        s1 = fmaf(mc, c, s1);
        s2 = fmaf(mc, c2, s2);
        float mcc = mc * c;
        s3 = fmaf(mcc, c2, s3);
        s4 = fmaf(mc * c2, c2, s4);

        // histogram with warp aggregation
        bool take = (mc > 0.5f) && (c >= -1.0f) && (c <= 1.0f);
        unsigned am = __ballot_sync(0xffffffffu, take);
        if (take) {
            int bi = (int)floorf(__fmul_rn(__fadd_rn(c, 1.0f), 25.0f));
            bi = min(max(bi, 0), 49);
            unsigned peers = __match_any_sync(am, bi);
            if ((int)(__ffs(peers) - 1) == tx)
                atomicAdd(&shHist[bi], (float)__popc(peers));
        }

        bool mb = mc > 0.5f;
        if (mb) {
            lbp[0] += (c - cnext > 0.0f) ? 1.0f : 0.0f;  // D +1
            lbp[1] += (c - cprev > 0.0f) ? 1.0f : 0.0f;  // D -1
            lbp[2] += (c - xyp  > 0.0f) ? 1.0f : 0.0f;   // H +1
            lbp[3] += (c - xym  > 0.0f) ? 1.0f : 0.0f;   // H -1
            lbp[4] += (c - xxp  > 0.0f) ? 1.0f : 0.0f;   // W +1
            lbp[5] += (c - xxm  > 0.0f) ? 1.0f : 0.0f;   // W -1
        }

        {   // GLCM D axis
            float mp = (mb && mnext > 0.5f) ? 1.0f : 0.0f;
            float d = c - cnext, dd = d * d;
            gs[0] += mp;
            gc[0] = fmaf(mp, dd, gc[0]);
            gh[0] = fmaf(mp, __fdividef(1.0f, 1.0f + dd), gh[0]);
        }
        {   // GLCM H axis
            float mp = (mb && myp > 0.5f) ? 1.0f : 0.0f;
            float d = c - xyp, dd = d * d;
            gs[1] += mp;
            gc[1] = fmaf(mp, dd, gc[1]);
            gh[1] = fmaf(mp, __fdividef(1.0f, 1.0f + dd), gh[1]);
        }
        {   // GLCM W axis
            float mp = (mb && mxp > 0.5f) ? 1.0f : 0.0f;
            float d = c - xxp, dd = d * d;
            gs[2] += mp;
            gc[2] = fmaf(mp, dd, gc[2]);
            gh[2] = fmaf(mp, __fdividef(1.0f, 1.0f + dd), gh[2]);
        }

        // rotate z registers
        cprev = c; c = cnext; mc = mnext;
        int zn = z + 2;
        if (zn < DD) {
            cnext = __ldg(X + base + (size_t)zn * HW);
            mnext = __ldg(M + base + (size_t)zn * HW);
        } else {
            cnext = 0.0f; mnext = 0.0f;
        }
    }

    float vals[20];
    vals[0] = n; vals[1] = s1; vals[2] = s2; vals[3] = s3; vals[4] = s4;
    #pragma unroll
    for (int k = 0; k < 6; k++) vals[5 + k] = lbp[k];
    #pragma unroll
    for (int a = 0; a < 3; a++) {
        vals[11 + 3 * a] = gs[a];
        vals[12 + 3 * a] = gc[a];
        vals[13 + 3 * a] = gh[a];
    }

    int lane = tid & 31, warp = tid >> 5;
    #pragma unroll
    for (int k = 0; k < 20; k++) {
        float v = vals[k];
        #pragma unroll
        for (int o = 16; o > 0; o >>= 1) v += __shfl_down_sync(0xffffffffu, v, o);
        if (lane == 0) red[k][warp] = v;
    }
    __syncthreads();

    if (tid < 20) {
        double acc = 0.0;
        #pragma unroll
        for (int w = 0; w < 8; w++) acc += (double)red[tid][w];
        int gi;
        if (tid < 5)       gi = tid;             // moments
        else if (tid < 11) gi = 13 + (tid - 5);  // lbp
        else {                                   // glcm
            int a = (tid - 11) / 3, r = (tid - 11) % 3;
            gi = 19 + 3 * a + r;
        }
        atomicAdd(&g_acc[b][gi], acc);
    }
    if (tid >= 64 && tid < 114)
        atomicAdd(&g_acc[b][NSCAL + tid - 64], (double)shHist[tid - 64]);
}

// ============================================================
// Finalize: 4 warps, one per batch; bins spread across lanes.
// ============================================================
__global__ void finalize_kernel(float* __restrict__ out) {
    int w = threadIdx.x >> 5, lane = threadIdx.x & 31;
    if (w >= BB) return;
    const double* a = g_acc[w];

    double tot = 0.0;
    for (int k = lane; k < 50; k += 32) tot += a[NSCAL + k];
    #pragma unroll
    for (int o = 16; o > 0; o >>= 1) tot += __shfl_down_sync(0xffffffffu, tot, o);
    tot = __shfl_sync(0xffffffffu, tot, 0);
    tot += 1e-8;

    double ent = 0.0;
    for (int k = lane; k < 50; k += 32) {
        double p = a[NSCAL + k] / tot;
        ent -= p * log(p + 1e-8);
    }
    #pragma unroll
    for (int o = 16; o > 0; o >>= 1) ent += __shfl_down_sync(0xffffffffu, ent, o);

    if (lane == 0) {
        double n = a[0];
        double nn = n > 1.0 ? n : 1.0;
        double mu = a[1] / nn;
        double M2 = a[2] - 2.0 * mu * a[1] + mu * mu * n;
        double nm1 = (n - 1.0) > 1.0 ? (n - 1.0) : 1.0;
        double var = M2 / nm1;
        double sigma = sqrt(var) + 1e-8;
        double M3 = a[3] - 3.0 * mu * a[2] + 3.0 * mu * mu * a[1] - mu * mu * mu * n;
        double M4 = a[4] - 4.0 * mu * a[3] + 6.0 * mu * mu * a[2]
                  - 4.0 * mu * mu * mu * a[1] + mu * mu * mu * mu * n;
        double sg3 = sigma * sigma * sigma;
        double skew = (M3 / sg3) / nn;
        double kurt = (M4 / (sg3 * sigma)) / nn - 3.0;
        double valid = (n >= 10.0) ? 1.0 : 0.0;

        float* o = out + w * 25;
        o[0] = (float)(mu * valid);
        o[1] = (float)(sigma * valid);
        o[2] = (float)(skew * valid);
        o[3] = (float)(kurt * valid);
        o[4] = (float)(ent * valid);
        for (int f = 0; f < 8; f++) o[5 + f] = (float)(a[5 + f] / nn);
        for (int k = 0; k < 6; k++) o[13 + k] = (float)(a[13 + k] / nn);
        for (int ax = 0; ax < 3; ax++) {
            double s = a[19 + 3 * ax];
            double ss = s > 1.0 ? s : 1.0;
            double ok = (s >= 4.0) ? 1.0 : 0.0;
            o[19 + 2 * ax]     = (float)((a[20 + 3 * ax] / ss) * ok);
            o[19 + 2 * ax + 1] = (float)((a[21 + 3 * ax] / ss) * ok);
        }
    }
}

extern "C" void kernel_launch(void* const* d_in, const int* in_sizes, int n_in,
                              void* d_out, int out_size) {
    const float* x  = (const float*)d_in[0];
    const float* m  = (const float*)d_in[1];
    const float* gf = (const float*)d_in[2];

    prep_kernel<<<1, 32>>>(gf);
    zero_kernel<<<1, 512>>>();

    dim3 gridA(WW / ATX, HH / ATY, BB);   // (5, 40, 4)
    dim3 blkA(ATX, ATY);
    gabor_kernel<<<gridA, blkA>>>(x, m);

    dim3 gridB(WW / 32, HH / 8, BB);      // (5, 20, 4)
    dim3 blkB(32, 8);
    stats_kernel<<<gridB, blkB>>>(x, m);

    finalize_kernel<<<1, 128>>>((float*)d_out);
}

// round 3
// speedup vs baseline: 2.4461x; 1.0982x over previous
#include <cuda_runtime.h>
#include <math.h>

#define BB 4
#define DD 96
#define HH 160
#define WW 160
#define HW (HH*WW)
#define NSCAL 28
#define NACC  78   // 28 scalars + 50 histogram bins

// Global accumulators (double) — zeroed every launch by zero_kernel.
__device__ double g_acc[BB][NACC];
// Derived separable gabor weights: u[f][j] (9 yx taps) and c[f] (box term).
__device__ float g_u[72];
__device__ float g_cf[8];

typedef unsigned long long u64t;
__device__ __forceinline__ u64t pack2(float lo, float hi) {
    u64t r; asm("mov.b64 %0,{%1,%2};" : "=l"(r) : "f"(lo), "f"(hi)); return r;
}
__device__ __forceinline__ void unpack2(float& lo, float& hi, u64t v) {
    asm("mov.b64 {%0,%1},%2;" : "=f"(lo), "=f"(hi) : "l"(v));
}
__device__ __forceinline__ void fma2(u64t& d, u64t a, u64t b) {
    asm("fma.rn.f32x2 %0,%1,%2,%0;" : "+l"(d) : "l"(a), "l"(b));
}

__global__ void zero_kernel() {
    int i = blockIdx.x * blockDim.x + threadIdx.x;
    if (i < BB * NACC) ((double*)g_acc)[i] = 0.0;
}

// Derive separable decomposition from the input gabor filters:
// F[dz][j] = gz[dz]*u[j] - c  with gz = [a,1,a], a = exp(-2).
__global__ void prep_kernel(const float* __restrict__ gf) {
    int f = threadIdx.x;
    if (f < 8) {
        const float A = 0.13533528323661270f;  // exp(-2)
        float cacc = 0.0f;
        #pragma unroll
        for (int j = 0; j < 9; j++) {
            float F1 = gf[f * 27 + 9 + j];
            float F0 = gf[f * 27 + j];
            float uj = (F1 - F0) * (1.0f / (1.0f - A));
            g_u[f * 9 + j] = uj;
            cacc += (uj - F1);
        }
        g_cf[f] = cacc * (1.0f / 9.0f);
    }
}

// ============================================================
// Kernel A: gabor features. smem x-tiles, 4-slot ring, 1 sync/z,
// packed f32x2 matvec. Z split into 2 chunks of 48 for occupancy.
// ============================================================
#define ATX 32
#define ATY 4
#define ANL ((ATY + 2) * (ATX + 2))   // 204
#define ZCHA 48                        // z-planes per block (2 chunks)

__global__ __launch_bounds__(128)
void gabor_kernel(const float* __restrict__ X, const float* __restrict__ M) {
    __shared__ float xs[4][ATY + 2][ATX + 2];
    __shared__ float red[8][4];
    const int tx = threadIdx.x, ty = threadIdx.y;
    const int tid = ty * ATX + tx;
    const int x0 = blockIdx.x * ATX, y0 = blockIdx.y * ATY;
    const int b = blockIdx.z >> 1;
    const int zs = (blockIdx.z & 1) * ZCHA;
    const float* Xb = X + (size_t)b * DD * HW;
    const float* Mb = M + (size_t)b * DD * HW;

    // packed weights: pair filters (2p, 2p+1)
    u64t u2[36];
    float cf[8];
    #pragma unroll
    for (int p = 0; p < 4; p++) {
        #pragma unroll
        for (int j = 0; j < 9; j++)
            u2[p * 9 + j] = pack2(g_u[(2 * p) * 9 + j], g_u[(2 * p + 1) * 9 + j]);
    }
    #pragma unroll
    for (int f = 0; f < 8; f++) cf[f] = g_cf[f];

    // precompute halo-load slots (z-invariant)
    int loff[2]; bool lval[2];
    #pragma unroll
    for (int s = 0; s < 2; s++) {
        int i = tid + s * 128;
        bool ok = (i < ANL);
        int ry = i / (ATX + 2), rx = i % (ATX + 2);
        int gy = y0 + ry - 1, gx = x0 + rx - 1;
        lval[s] = ok && gy >= 0 && gy < HH && gx >= 0 && gx < WW;
        loff[s] = gy * WW + gx;
    }

    // preload planes zs-1 (slot 3), zs (slot 0), zs+1 (slot 1).
    // zs multiple of 48 => (zs-1)&3==3, zs&3==0, (zs+1)&3==1.
    #pragma unroll
    for (int s = 0; s < 2; s++) {
        int i = tid + s * 128;
        if (i < ANL) {
            float vp = 0.0f;
            if (zs > 0 && lval[s]) vp = __ldg(Xb + (size_t)(zs - 1) * HW + loff[s]);
            (&xs[3][0][0])[i] = vp;
            (&xs[0][0][0])[i] = lval[s] ? __ldg(Xb + (size_t)zs * HW + loff[s]) : 0.0f;
            (&xs[1][0][0])[i] = lval[s] ? __ldg(Xb + (size_t)(zs + 1) * HW + loff[s]) : 0.0f;
        }
    }

    const float A = 0.13533528323661270f;
    float gab[8] = {0, 0, 0, 0, 0, 0, 0, 0};
    const int moff = (y0 + ty) * WW + x0 + tx;

    for (int z = zs; z < zs + ZCHA; z++) {
        __syncthreads();
        // stage plane z+2 into registers (overlaps LDG latency with compute)
        float st0 = 0.0f, st1 = 0.0f;
        {
            int zq = z + 2;
            if (zq < DD) {
                const float* P = Xb + (size_t)zq * HW;
                if (lval[0]) st0 = __ldg(P + loff[0]);
                if (lval[1]) st1 = __ldg(P + loff[1]);
            }
        }
        float mc = __ldg(Mb + (size_t)z * HW + moff);

        const int sm1 = (z + 3) & 3, sc = z & 3, sp1 = (z + 1) & 3;
        float box = 0.0f;
        u64t g2[4] = {0ull, 0ull, 0ull, 0ull};
        #pragma unroll
        for (int dy = 0; dy < 3; dy++) {
            #pragma unroll
            for (int dx = 0; dx < 3; dx++) {
                float xm = xs[sm1][ty + dy][tx + dx];
                float xc = xs[sc ][ty + dy][tx + dx];
                float xp = xs[sp1][ty + dy][tx + dx];
                float mp2 = xm + xp;
                float tz = fmaf(A, mp2, xc);
                box += mp2 + xc;
                u64t tzz = pack2(tz, tz);
                const int j = dy * 3 + dx;
                fma2(g2[0], u2[0 * 9 + j], tzz);
                fma2(g2[1], u2[1 * 9 + j], tzz);
                fma2(g2[2], u2[2 * 9 + j], tzz);
                fma2(g2[3], u2[3 * 9 + j], tzz);
            }
        }
        float g[8];
        unpack2(g[0], g[1], g2[0]);
        unpack2(g[2], g[3], g2[1]);
        unpack2(g[4], g[5], g2[2]);
        unpack2(g[6], g[7], g2[3]);
        #pragma unroll
        for (int f = 0; f < 8; f++) {
            float gv = fmaf(-cf[f], box, g[f]);
            gab[f] = fmaf(fabsf(gv), mc, gab[f]);
        }

        // store staged plane into slot (z+2)&3 — not read by compute(z)
        {
            int sw = (z + 2) & 3;
            float* bs = &xs[sw][0][0];
            bs[tid] = st0;                      // tid < 204 always
            if (tid + 128 < ANL) bs[tid + 128] = st1;
        }
    }

    int lane = tid & 31, warp = tid >> 5;
    #pragma unroll
    for (int f = 0; f < 8; f++) {
        float v = gab[f];
        #pragma unroll
        for (int o = 16; o > 0; o >>= 1) v += __shfl_down_sync(0xffffffffu, v, o);
        if (lane == 0) red[f][warp] = v;
    }
    __syncthreads();
    if (tid < 8) {
        double acc = (double)red[tid][0] + (double)red[tid][1]
                   + (double)red[tid][2] + (double)red[tid][3];
        atomicAdd(&g_acc[b][5 + tid], acc);
    }
}

// ============================================================
// Kernel B: moments/hist/lbp/glcm. z-register rotation, x-neighbors
// via warp shuffles. Z split into 4 chunks of 24 for occupancy.
// ============================================================
#define ZCHB 24

__global__ __launch_bounds__(256)
void stats_kernel(const float* __restrict__ X, const float* __restrict__ M) {
    __shared__ float shHist[50];
    __shared__ float red[20][8];
    const int tx = threadIdx.x, ty = threadIdx.y;
    const int tid = ty * 32 + tx;
    const int x = blockIdx.x * 32 + tx, y = blockIdx.y * 8 + ty;
    const int b = blockIdx.z >> 2;
    const int z0 = (blockIdx.z & 3) * ZCHB;
    if (tid < 50) shHist[tid] = 0.0f;
    __syncthreads();

    const size_t base = (size_t)b * DD * HW + (size_t)y * WW + x;
    const bool xpok = (x + 1 < WW), xmok = (x > 0);
    const bool ypok = (y + 1 < HH), ymok = (y > 0);

    float cprev = (z0 > 0) ? __ldg(X + base + (size_t)(z0 - 1) * HW) : 0.0f;
    float c     = __ldg(X + base + (size_t)z0 * HW);
    float mc    = __ldg(M + base + (size_t)z0 * HW);
    float cnext = __ldg(X + base + (size_t)(z0 + 1) * HW);
    float mnext = __ldg(M + base + (size_t)(z0 + 1) * HW);

    float n = 0, s1 = 0, s2 = 0, s3 = 0, s4 = 0;
    float lbp[6] = {0, 0, 0, 0, 0, 0};
    float gs[3] = {0, 0, 0}, gc[3] = {0, 0, 0}, gh[3] = {0, 0, 0};

    for (int z = z0; z < z0 + ZCHB; z++) {
        size_t o = base + (size_t)z * HW;
        // y-neighbors: LDG (other rows)
        float xyp = ypok ? __ldg(X + o + WW) : 0.0f;
        float xym = ymok ? __ldg(X + o - WW) : 0.0f;
        float myp = ypok ? __ldg(M + o + WW) : 0.0f;
        // x-neighbors: lane shuffles, boundary lanes via predicated LDG
        float xxm = __shfl_up_sync(0xffffffffu, c, 1);
        float xxp = __shfl_down_sync(0xffffffffu, c, 1);
        float mxp = __shfl_down_sync(0xffffffffu, mc, 1);
        if (tx == 0)  xxm = xmok ? __ldg(X + o - 1) : 0.0f;
        if (tx == 31) {
            xxp = xpok ? __ldg(X + o + 1) : 0.0f;
            mxp = xpok ? __ldg(M + o + 1) : 0.0f;
        }

        // moments
        float c2 = c * c;
        n += mc;
        s1 = fmaf(mc, c, s1);
        s2 = fmaf(mc, c2, s2);
        float mcc = mc * c;
        s3 = fmaf(mcc, c2, s3);
        s4 = fmaf(mc * c2, c2, s4);

        // histogram with warp aggregation
        bool take = (mc > 0.5f) && (c >= -1.0f) && (c <= 1.0f);
        unsigned am = __ballot_sync(0xffffffffu, take);
        if (take) {
            int bi = (int)floorf(__fmul_rn(__fadd_rn(c, 1.0f), 25.0f));
            bi = min(max(bi, 0), 49);
            unsigned peers = __match_any_sync(am, bi);
            if ((int)(__ffs(peers) - 1) == tx)
                atomicAdd(&shHist[bi], (float)__popc(peers));
        }

        bool mb = mc > 0.5f;
        if (mb) {
            lbp[0] += (c - cnext > 0.0f) ? 1.0f : 0.0f;  // D +1
            lbp[1] += (c - cprev > 0.0f) ? 1.0f : 0.0f;  // D -1
            lbp[2] += (c - xyp  > 0.0f) ? 1.0f : 0.0f;   // H +1
            lbp[3] += (c - xym  > 0.0f) ? 1.0f : 0.0f;   // H -1
            lbp[4] += (c - xxp  > 0.0f) ? 1.0f : 0.0f;   // W +1
            lbp[5] += (c - xxm  > 0.0f) ? 1.0f : 0.0f;   // W -1
        }

        {   // GLCM D axis
            float mp = (mb && mnext > 0.5f) ? 1.0f : 0.0f;
            float d = c - cnext, dd = d * d;
            gs[0] += mp;
            gc[0] = fmaf(mp, dd, gc[0]);
            gh[0] = fmaf(mp, __fdividef(1.0f, 1.0f + dd), gh[0]);
        }
        {   // GLCM H axis
            float mp = (mb && myp > 0.5f) ? 1.0f : 0.0f;
            float d = c - xyp, dd = d * d;
            gs[1] += mp;
            gc[1] = fmaf(mp, dd, gc[1]);
            gh[1] = fmaf(mp, __fdividef(1.0f, 1.0f + dd), gh[1]);
        }
        {   // GLCM W axis
            float mp = (mb && mxp > 0.5f) ? 1.0f : 0.0f;
            float d = c - xxp, dd = d * d;
            gs[2] += mp;
            gc[2] = fmaf(mp, dd, gc[2]);
            gh[2] = fmaf(mp, __fdividef(1.0f, 1.0f + dd), gh[2]);
        }

        // rotate z registers
        cprev = c; c = cnext; mc = mnext;
        int zn = z + 2;
        if (zn < DD) {
            cnext = __ldg(X + base + (size_t)zn * HW);
            mnext = __ldg(M + base + (size_t)zn * HW);
        } else {
            cnext = 0.0f; mnext = 0.0f;
        }
    }

    float vals[20];
    vals[0] = n; vals[1] = s1; vals[2] = s2; vals[3] = s3; vals[4] = s4;
    #pragma unroll
    for (int k = 0; k < 6; k++) vals[5 + k] = lbp[k];
    #pragma unroll
    for (int a = 0; a < 3; a++) {
        vals[11 + 3 * a] = gs[a];
        vals[12 + 3 * a] = gc[a];
        vals[13 + 3 * a] = gh[a];
    }

    int lane = tid & 31, warp = tid >> 5;
    #pragma unroll
    for (int k = 0; k < 20; k++) {
        float v = vals[k];
        #pragma unroll
        for (int o = 16; o > 0; o >>= 1) v += __shfl_down_sync(0xffffffffu, v, o);
        if (lane == 0) red[k][warp] = v;
    }
    __syncthreads();

    if (tid < 20) {
        double acc = 0.0;
        #pragma unroll
        for (int w = 0; w < 8; w++) acc += (double)red[tid][w];
        int gi;
        if (tid < 5)       gi = tid;             // moments
        else if (tid < 11) gi = 13 + (tid - 5);  // lbp
        else {                                   // glcm
            int a = (tid - 11) / 3, r = (tid - 11) % 3;
            gi = 19 + 3 * a + r;
        }
        atomicAdd(&g_acc[b][gi], acc);
    }
    if (tid >= 64 && tid < 114)
        atomicAdd(&g_acc[b][NSCAL + tid - 64], (double)shHist[tid - 64]);
}

// ============================================================
// Finalize: 4 warps, one per batch; bins spread across lanes.
// ============================================================
__global__ void finalize_kernel(float* __restrict__ out) {
    int w = threadIdx.x >> 5, lane = threadIdx.x & 31;
    if (w >= BB) return;
    const double* a = g_acc[w];

    double tot = 0.0;
    for (int k = lane; k < 50; k += 32) tot += a[NSCAL + k];
    #pragma unroll
    for (int o = 16; o > 0; o >>= 1) tot += __shfl_down_sync(0xffffffffu, tot, o);
    tot = __shfl_sync(0xffffffffu, tot, 0);
    tot += 1e-8;

    double ent = 0.0;
    for (int k = lane; k < 50; k += 32) {
        double p = a[NSCAL + k] / tot;
        ent -= p * log(p + 1e-8);
    }
    #pragma unroll
    for (int o = 16; o > 0; o >>= 1) ent += __shfl_down_sync(0xffffffffu, ent, o);

    if (lane == 0) {
        double n = a[0];
        double nn = n > 1.0 ? n : 1.0;
        double mu = a[1] / nn;
        double M2 = a[2] - 2.0 * mu * a[1] + mu * mu * n;
        double nm1 = (n - 1.0) > 1.0 ? (n - 1.0) : 1.0;
        double var = M2 / nm1;
        double sigma = sqrt(var) + 1e-8;
        double M3 = a[3] - 3.0 * mu * a[2] + 3.0 * mu * mu * a[1] - mu * mu * mu * n;
        double M4 = a[4] - 4.0 * mu * a[3] + 6.0 * mu * mu * a[2]
                  - 4.0 * mu * mu * mu * a[1] + mu * mu * mu * mu * n;
        double sg3 = sigma * sigma * sigma;
        double skew = (M3 / sg3) / nn;
        double kurt = (M4 / (sg3 * sigma)) / nn - 3.0;
        double valid = (n >= 10.0) ? 1.0 : 0.0;

        float* o = out + w * 25;
        o[0] = (float)(mu * valid);
        o[1] = (float)(sigma * valid);
        o[2] = (float)(skew * valid);
        o[3] = (float)(kurt * valid);
        o[4] = (float)(ent * valid);
        for (int f = 0; f < 8; f++) o[5 + f] = (float)(a[5 + f] / nn);
        for (int k = 0; k < 6; k++) o[13 + k] = (float)(a[13 + k] / nn);
        for (int ax = 0; ax < 3; ax++) {
            double s = a[19 + 3 * ax];
            double ss = s > 1.0 ? s : 1.0;
            double ok = (s >= 4.0) ? 1.0 : 0.0;
            o[19 + 2 * ax]     = (float)((a[20 + 3 * ax] / ss) * ok);
            o[19 + 2 * ax + 1] = (float)((a[21 + 3 * ax] / ss) * ok);
        }
    }
}

extern "C" void kernel_launch(void* const* d_in, const int* in_sizes, int n_in,
                              void* d_out, int out_size) {
    const float* x  = (const float*)d_in[0];
    const float* m  = (const float*)d_in[1];
    const float* gf = (const float*)d_in[2];

    prep_kernel<<<1, 32>>>(gf);
    zero_kernel<<<1, 512>>>();

    dim3 gridA(WW / ATX, HH / ATY, BB * 2);   // (5, 40, 8)  = 1600 CTAs
    dim3 blkA(ATX, ATY);
    gabor_kernel<<<gridA, blkA>>>(x, m);

    dim3 gridB(WW / 32, HH / 8, BB * 4);      // (5, 20, 16) = 1600 CTAs
    dim3 blkB(32, 8);
    stats_kernel<<<gridB, blkB>>>(x, m);

    finalize_kernel<<<1, 128>>>((float*)d_out);
}

// round 5
// speedup vs baseline: 2.8196x; 1.1527x over previous
#include <cuda_runtime.h>
#include <math.h>

#define BB 4
#define DD 96
#define HH 160
#define WW 160
#define HW (HH*WW)
#define NSCAL 28
#define NACC  78   // 28 scalars + 50 histogram bins

// Global accumulators (double) — zeroed by prep_kernel each launch.
__device__ double g_acc[BB][NACC];
// Symmetric-folded gabor 2D weights (5 groups) + box coefficient.
__device__ float g_w[8][5];
__device__ float g_cf[8];

typedef unsigned long long u64t;
__device__ __forceinline__ u64t pack2(float lo, float hi) {
    u64t r; asm("mov.b64 %0,{%1,%2};" : "=l"(r) : "f"(lo), "f"(hi)); return r;
}
__device__ __forceinline__ void unpack2(float& lo, float& hi, u64t v) {
    asm("mov.b64 {%0,%1},%2;" : "=f"(lo), "=f"(hi) : "l"(v));
}
__device__ __forceinline__ void fma2(u64t& d, u64t a, u64t b) {
    asm("fma.rn.f32x2 %0,%1,%2,%0;" : "+l"(d) : "l"(a), "l"(b));
}

// ============================================================
// prep: zero accumulators + derive weights.
// F[dz][j] = gz[dz]*u[j] - c, gz=[a,1,a], a=exp(-2)
//  => u[j] = (F1[j]-F0[j])/(1-a),  cf = mean_j(u[j]-F1[j])
// conv_f = sum_j u[j]*t[j] - cf*box     (box = plain 27-sum)
// 2D profile symmetric (u[j]==u[8-j]):
// conv_f = sum_{k<4} ubar_k*(t_k+t_{8-k}) + u_4*t_4 - cf*box
// ============================================================
__global__ void prep_kernel(const float* __restrict__ gf) {
    int t = threadIdx.x;
    if (t < BB * NACC) ((double*)g_acc)[t] = 0.0;
    if (t >= 320 && t < 328) {
        int f = t - 320;
        const float A = 0.13533528323661270f;  // exp(-2)
        float u[9], cacc = 0.0f;
        #pragma unroll
        for (int j = 0; j < 9; j++) {
            float F1 = gf[f * 27 + 9 + j];
            float F0 = gf[f * 27 + j];
            u[j] = (F1 - F0) * (1.0f / (1.0f - A));
            cacc += (u[j] - F1);
        }
        g_cf[f] = cacc * (1.0f / 9.0f);
        g_w[f][0] = (u[0] + u[8]) * 0.5f;
        g_w[f][1] = (u[1] + u[7]) * 0.5f;
        g_w[f][2] = (u[2] + u[6]) * 0.5f;
        g_w[f][3] = (u[3] + u[5]) * 0.5f;
        g_w[f][4] = u[4];
    }
}

// ============================================================
// Fused kernel: gabor + moments + hist + lbp + glcm in one pass.
// 32x8 xy-tile, 24-plane z-chunk, 4-slot smem ring, 1 sync/z.
// ============================================================
#define TXX 32
#define TYY 8
#define ZCH 24
#define ANL ((TYY + 2) * (TXX + 2))   // 340

__global__ __launch_bounds__(256, 2)
void fused_kernel(const float* __restrict__ X, const float* __restrict__ M) {
    __shared__ float xs[4][TYY + 2][TXX + 2];
    __shared__ float msh[4][TYY + 2][TXX + 2];
    __shared__ float shHist[8][50];
    __shared__ float red[NSCAL][8];

    const int tx = threadIdx.x, ty = threadIdx.y;
    const int tid = ty * TXX + tx;
    const int warp = tid >> 5, lane = tid & 31;
    const int x0 = blockIdx.x * TXX, y0 = blockIdx.y * TYY;
    const int b = blockIdx.z >> 2;
    const int zs = (blockIdx.z & 3) * ZCH;      // 24 % 4 == 0 -> zs & 3 == 0
    const float* Xb = X + (size_t)b * DD * HW;
    const float* Mb = M + (size_t)b * DD * HW;

    for (int i = tid; i < 400; i += 256) ((float*)shHist)[i] = 0.0f;

    // packed weights: pair filters (2p, 2p+1); 5 sym taps + (-cf) box coeff
    u64t w2[20], cf2[4];
    #pragma unroll
    for (int p = 0; p < 4; p++) {
        #pragma unroll
        for (int k = 0; k < 5; k++)
            w2[p * 5 + k] = pack2(g_w[2 * p][k], g_w[2 * p + 1][k]);
        cf2[p] = pack2(-g_cf[2 * p], -g_cf[2 * p + 1]);
    }

    // halo-load slots (z-invariant)
    int loff[2]; bool lval[2];
    #pragma unroll
    for (int s = 0; s < 2; s++) {
        int i = tid + s * 256;
        bool ok = (i < ANL);
        int ry = i / (TXX + 2), rx = i % (TXX + 2);
        int gy = y0 + ry - 1, gx = x0 + rx - 1;
        lval[s] = ok && gy >= 0 && gy < HH && gx >= 0 && gx < WW;
        loff[s] = gy * WW + gx;
    }

    // preload planes zs-1 (slot 3), zs (slot 0), zs+1 (slot 1)
    #pragma unroll
    for (int s = 0; s < 2; s++) {
        int i = tid + s * 256;
        if (i < ANL) {
            float xpv = 0.0f, mpv = 0.0f;
            if (zs > 0 && lval[s]) {
                xpv = __ldg(Xb + (size_t)(zs - 1) * HW + loff[s]);
                mpv = __ldg(Mb + (size_t)(zs - 1) * HW + loff[s]);
            }
            (&xs[3][0][0])[i] = xpv;
            (&msh[3][0][0])[i] = mpv;
            (&xs[0][0][0])[i]  = lval[s] ? __ldg(Xb + (size_t)zs * HW + loff[s]) : 0.0f;
            (&msh[0][0][0])[i] = lval[s] ? __ldg(Mb + (size_t)zs * HW + loff[s]) : 0.0f;
            (&xs[1][0][0])[i]  = lval[s] ? __ldg(Xb + (size_t)(zs + 1) * HW + loff[s]) : 0.0f;
            (&msh[1][0][0])[i] = lval[s] ? __ldg(Mb + (size_t)(zs + 1) * HW + loff[s]) : 0.0f;
        }
    }

    const float A = 0.13533528323661270f;
    const u64t ABSM = 0x7FFFFFFF7FFFFFFFull;
    u64t gab2[4] = {0ull, 0ull, 0ull, 0ull};
    float n = 0, m1 = 0, m2 = 0, m3 = 0, m4 = 0;
    float lbp[6] = {0, 0, 0, 0, 0, 0};
    float gs[3] = {0, 0, 0}, gc[3] = {0, 0, 0}, gh[3] = {0, 0, 0};

    for (int z = zs; z < zs + ZCH; z++) {
        __syncthreads();
        // stage plane z+2 (x and mask) in registers
        float sx0 = 0, sx1 = 0, sm0 = 0, sm1v = 0;
        {
            int zq = z + 2;
            if (zq < DD) {
                const float* Px = Xb + (size_t)zq * HW;
                const float* Pm = Mb + (size_t)zq * HW;
                if (lval[0]) { sx0 = __ldg(Px + loff[0]); sm0  = __ldg(Pm + loff[0]); }
                if (lval[1]) { sx1 = __ldg(Px + loff[1]); sm1v = __ldg(Pm + loff[1]); }
            }
        }

        const int q0 = (z + 3) & 3, q1 = z & 3, q2 = (z + 1) & 3;

        // 27 taps -> z-collapsed t[9] + plain box sum; capture raw neighbors
        float t[9], box = 0.0f;
        float c = 0, xup = 0, xdn = 0, xym = 0, xxm = 0, xxp = 0, xyp = 0;
        #pragma unroll
        for (int dy = 0; dy < 3; dy++) {
            #pragma unroll
            for (int dx = 0; dx < 3; dx++) {
                const int j = dy * 3 + dx;
                float xm = xs[q0][ty + dy][tx + dx];
                float xc = xs[q1][ty + dy][tx + dx];
                float xp = xs[q2][ty + dy][tx + dx];
                float mp2 = xm + xp;
                t[j] = fmaf(A, mp2, xc);
                box += mp2 + xc;
                if (dy == 0 && dx == 1) xym = xc;
                if (dy == 1 && dx == 0) xxm = xc;
                if (dy == 1 && dx == 1) { c = xc; xdn = xm; xup = xp; }
                if (dy == 1 && dx == 2) xxp = xc;
                if (dy == 2 && dx == 1) xyp = xc;
            }
        }
        float ts0 = t[0] + t[8], ts1 = t[1] + t[7];
        float ts2 = t[2] + t[6], ts3 = t[3] + t[5], ts4 = t[4];
        u64t T0 = pack2(ts0, ts0), T1 = pack2(ts1, ts1), T2 = pack2(ts2, ts2);
        u64t T3 = pack2(ts3, ts3), T4 = pack2(ts4, ts4);
        u64t BX = pack2(box, box);

        u64t g2[4];
        #pragma unroll
        for (int p = 0; p < 4; p++) {
            u64t acc = 0ull;
            fma2(acc, w2[p * 5 + 0], T0);
            fma2(acc, w2[p * 5 + 1], T1);
            fma2(acc, w2[p * 5 + 2], T2);
            fma2(acc, w2[p * 5 + 3], T3);
            fma2(acc, w2[p * 5 + 4], T4);
            fma2(acc, cf2[p], BX);          // - cf * box
            g2[p] = acc;
        }

        float mc  = msh[q1][ty + 1][tx + 1];
        float mzp = msh[q2][ty + 1][tx + 1];
        float myp = msh[q1][ty + 2][tx + 1];
        float mxp = msh[q1][ty + 1][tx + 2];

        u64t mcp = pack2(mc, mc);
        #pragma unroll
        for (int p = 0; p < 4; p++) {
            u64t ga = g2[p] & ABSM;         // |gv| packed
            fma2(gab2[p], ga, mcp);
        }

        // moments
        float c2 = c * c;
        n += mc;
        m1 = fmaf(mc, c, m1);
        m2 = fmaf(mc, c2, m2);
        float mcc = mc * c;
        m3 = fmaf(mcc, c2, m3);
        m4 = fmaf(mc * c2, c2, m4);

        // histogram: per-warp smem hist, plain atomic
        if (mc > 0.5f && c >= -1.0f && c <= 1.0f) {
            int bi = (int)floorf(__fmul_rn(__fadd_rn(c, 1.0f), 25.0f));
            bi = min(max(bi, 0), 49);
            atomicAdd(&shHist[warp][bi], 1.0f);
        }

        bool mb = mc > 0.5f;
        if (mb) {
            lbp[0] += (c - xup > 0.0f) ? 1.0f : 0.0f;
            lbp[1] += (c - xdn > 0.0f) ? 1.0f : 0.0f;
            lbp[2] += (c - xyp > 0.0f) ? 1.0f : 0.0f;
            lbp[3] += (c - xym > 0.0f) ? 1.0f : 0.0f;
            lbp[4] += (c - xxp > 0.0f) ? 1.0f : 0.0f;
            lbp[5] += (c - xxm > 0.0f) ? 1.0f : 0.0f;
        }

        {   // GLCM D
            float mp = (mb && mzp > 0.5f) ? 1.0f : 0.0f;
            float d = c - xup, dd = d * d;
            gs[0] += mp;
            gc[0] = fmaf(mp, dd, gc[0]);
            gh[0] = fmaf(mp, __fdividef(1.0f, 1.0f + dd), gh[0]);
        }
        {   // GLCM H
            float mp = (mb && myp > 0.5f) ? 1.0f : 0.0f;
            float d = c - xyp, dd = d * d;
            gs[1] += mp;
            gc[1] = fmaf(mp, dd, gc[1]);
            gh[1] = fmaf(mp, __fdividef(1.0f, 1.0f + dd), gh[1]);
        }
        {   // GLCM W
            float mp = (mb && mxp > 0.5f) ? 1.0f : 0.0f;
            float d = c - xxp, dd = d * d;
            gs[2] += mp;
            gc[2] = fmaf(mp, dd, gc[2]);
            gh[2] = fmaf(mp, __fdividef(1.0f, 1.0f + dd), gh[2]);
        }

        // store staged plane into slot (z+2)&3 (not read this iteration)
        {
            int sw = (z + 2) & 3;
            float* bx = &xs[sw][0][0];
            float* bm = &msh[sw][0][0];
            bx[tid] = sx0; bm[tid] = sm0;
            if (tid + 256 < ANL) { bx[tid + 256] = sx1; bm[tid + 256] = sm1v; }
        }
    }

    // ---- block reduction ----
    float gabf[8];
    unpack2(gabf[0], gabf[1], gab2[0]);
    unpack2(gabf[2], gabf[3], gab2[1]);
    unpack2(gabf[4], gabf[5], gab2[2]);
    unpack2(gabf[6], gabf[7], gab2[3]);

    float vals[NSCAL];
    vals[0] = n; vals[1] = m1; vals[2] = m2; vals[3] = m3; vals[4] = m4;
    #pragma unroll
    for (int f = 0; f < 8; f++) vals[5 + f] = gabf[f];
    #pragma unroll
    for (int k = 0; k < 6; k++) vals[13 + k] = lbp[k];
    #pragma unroll
    for (int a = 0; a < 3; a++) {
        vals[19 + 3 * a] = gs[a];
        vals[20 + 3 * a] = gc[a];
        vals[21 + 3 * a] = gh[a];
    }

    #pragma unroll
    for (int k = 0; k < NSCAL; k++) {
        float v = vals[k];
        #pragma unroll
        for (int o = 16; o > 0; o >>= 1) v += __shfl_down_sync(0xffffffffu, v, o);
        if (lane == 0) red[k][warp] = v;
    }
    __syncthreads();

    if (tid < NSCAL) {
        double acc = 0.0;
        #pragma unroll
        for (int w = 0; w < 8; w++) acc += (double)red[tid][w];
        atomicAdd(&g_acc[b][tid], acc);
    }
    if (tid >= 64 && tid < 114) {
        int hb = tid - 64;
        float hv = 0.0f;
        #pragma unroll
        for (int w = 0; w < 8; w++) hv += shHist[w][hb];
        atomicAdd(&g_acc[b][NSCAL + hb], (double)hv);
    }
}

// ============================================================
// Finalize: 4 warps, one per batch; bins spread across lanes.
// ============================================================
__global__ void finalize_kernel(float* __restrict__ out) {
    int w = threadIdx.x >> 5, lane = threadIdx.x & 31;
    if (w >= BB) return;
    const double* a = g_acc[w];

    double tot = 0.0;
    for (int k = lane; k < 50; k += 32) tot += a[NSCAL + k];
    #pragma unroll
    for (int o = 16; o > 0; o >>= 1) tot += __shfl_down_sync(0xffffffffu, tot, o);
    tot = __shfl_sync(0xffffffffu, tot, 0);
    tot += 1e-8;

    double ent = 0.0;
    for (int k = lane; k < 50; k += 32) {
        double p = a[NSCAL + k] / tot;
        ent -= p * log(p + 1e-8);
    }
    #pragma unroll
    for (int o = 16; o > 0; o >>= 1) ent += __shfl_down_sync(0xffffffffu, ent, o);

    if (lane == 0) {
        double n = a[0];
        double nn = n > 1.0 ? n : 1.0;
        double mu = a[1] / nn;
        double M2 = a[2] - 2.0 * mu * a[1] + mu * mu * n;
        double nm1 = (n - 1.0) > 1.0 ? (n - 1.0) : 1.0;
        double var = M2 / nm1;
        double sigma = sqrt(var) + 1e-8;
        double M3 = a[3] - 3.0 * mu * a[2] + 3.0 * mu * mu * a[1] - mu * mu * mu * n;
        double M4 = a[4] - 4.0 * mu * a[3] + 6.0 * mu * mu * a[2]
                  - 4.0 * mu * mu * mu * a[1] + mu * mu * mu * mu * n;
        double sg3 = sigma * sigma * sigma;
        double skew = (M3 / sg3) / nn;
        double kurt = (M4 / (sg3 * sigma)) / nn - 3.0;
        double valid = (n >= 10.0) ? 1.0 : 0.0;

        float* o = out + w * 25;
        o[0] = (float)(mu * valid);
        o[1] = (float)(sigma * valid);
        o[2] = (float)(skew * valid);
        o[3] = (float)(kurt * valid);
        o[4] = (float)(ent * valid);
        for (int f = 0; f < 8; f++) o[5 + f] = (float)(a[5 + f] / nn);
        for (int k = 0; k < 6; k++) o[13 + k] = (float)(a[13 + k] / nn);
        for (int ax = 0; ax < 3; ax++) {
            double s = a[19 + 3 * ax];
            double ss = s > 1.0 ? s : 1.0;
            double ok = (s >= 4.0) ? 1.0 : 0.0;
            o[19 + 2 * ax]     = (float)((a[20 + 3 * ax] / ss) * ok);
            o[19 + 2 * ax + 1] = (float)((a[21 + 3 * ax] / ss) * ok);
        }
    }
}

extern "C" void kernel_launch(void* const* d_in, const int* in_sizes, int n_in,
                              void* d_out, int out_size) {
    const float* x  = (const float*)d_in[0];
    const float* m  = (const float*)d_in[1];
    const float* gf = (const float*)d_in[2];

    prep_kernel<<<1, 352>>>(gf);

    dim3 grid(WW / TXX, HH / TYY, BB * 4);  // (5, 20, 16) = 1600 CTAs
    dim3 blk(TXX, TYY);
    fused_kernel<<<grid, blk>>>(x, m);

    finalize_kernel<<<1, 128>>>((float*)d_out);
}

// round 6
// speedup vs baseline: 3.0304x; 1.0748x over previous
#include <cuda_runtime.h>
#include <math.h>

#define BB 4
#define DD 96
#define HH 160
#define WW 160
#define HW (HH*WW)
#define NSCAL 28
#define NACC  78   // 28 scalars + 50 histogram bins

// Global accumulators (double) — zeroed by prep_kernel each launch.
__device__ double g_acc[BB][NACC];
// Symmetric-folded gabor 2D weights (5 groups) + box coefficient.
__device__ float g_w[8][5];
__device__ float g_cf[8];

typedef unsigned long long u64t;
__device__ __forceinline__ u64t pack2(float lo, float hi) {
    u64t r; asm("mov.b64 %0,{%1,%2};" : "=l"(r) : "f"(lo), "f"(hi)); return r;
}
__device__ __forceinline__ void unpack2(float& lo, float& hi, u64t v) {
    asm("mov.b64 {%0,%1},%2;" : "=f"(lo), "=f"(hi) : "l"(v));
}
__device__ __forceinline__ void fma2(u64t& d, u64t a, u64t b) {
    asm("fma.rn.f32x2 %0,%1,%2,%0;" : "+l"(d) : "l"(a), "l"(b));
}

// ============================================================
// prep: zero accumulators + derive weights.
// F[dz][j] = gz[dz]*u[j] - c, gz=[a,1,a], a=exp(-2)
//  => u[j] = (F1[j]-F0[j])/(1-a),  cf = mean_j(u[j]-F1[j])
// conv_f = sum_j u[j]*t[j] - cf*box     (box = plain 27-sum)
// 2D profile symmetric (u[j]==u[8-j]):
// conv_f = sum_{k<4} ubar_k*(t_k+t_{8-k}) + u_4*t_4 - cf*box
// ============================================================
__global__ void prep_kernel(const float* __restrict__ gf) {
    int t = threadIdx.x;
    if (t < BB * NACC) ((double*)g_acc)[t] = 0.0;
    if (t >= 320 && t < 328) {
        int f = t - 320;
        const float A = 0.13533528323661270f;  // exp(-2)
        float u[9], cacc = 0.0f;
        #pragma unroll
        for (int j = 0; j < 9; j++) {
            float F1 = gf[f * 27 + 9 + j];
            float F0 = gf[f * 27 + j];
            u[j] = (F1 - F0) * (1.0f / (1.0f - A));
            cacc += (u[j] - F1);
        }
        g_cf[f] = cacc * (1.0f / 9.0f);
        g_w[f][0] = (u[0] + u[8]) * 0.5f;
        g_w[f][1] = (u[1] + u[7]) * 0.5f;
        g_w[f][2] = (u[2] + u[6]) * 0.5f;
        g_w[f][3] = (u[3] + u[5]) * 0.5f;
        g_w[f][4] = u[4];
    }
}

// ============================================================
// Fused kernel. Raw ring holds (x,mask) float2 (4 slots).
// Aux ring holds per-cell z-collapsed (t,s) float2 (2 slots),
// computed ONCE per cell by the staging threads from their
// register x-history, instead of per-voxel (9x reuse).
// ============================================================
#define TXX 32
#define TYY 8
#define ZCH 24
#define ANL ((TYY + 2) * (TXX + 2))   // 340

__global__ __launch_bounds__(256)
void fused_kernel(const float* __restrict__ X, const float* __restrict__ M) {
    __shared__ float2 raw[4][TYY + 2][TXX + 2];   // (x, m)
    __shared__ float2 aux[2][TYY + 2][TXX + 2];   // (t, s)
    __shared__ float shHist[8][50];
    __shared__ float red[NSCAL][8];

    const int tx = threadIdx.x, ty = threadIdx.y;
    const int tid = ty * TXX + tx;
    const int warp = tid >> 5, lane = tid & 31;
    const int x0 = blockIdx.x * TXX, y0 = blockIdx.y * TYY;
    const int b = blockIdx.z >> 2;
    const int zs = (blockIdx.z & 3) * ZCH;      // 24 % 4 == 0 -> zs & 3 == 0, zs even
    const float* Xb = X + (size_t)b * DD * HW;
    const float* Mb = M + (size_t)b * DD * HW;

    for (int i = tid; i < 400; i += 256) ((float*)shHist)[i] = 0.0f;

    // packed weights: pair filters (2p, 2p+1); 5 sym taps + (-cf) box coeff
    u64t w2[20], cf2[4];
    #pragma unroll
    for (int p = 0; p < 4; p++) {
        #pragma unroll
        for (int k = 0; k < 5; k++)
            w2[p * 5 + k] = pack2(g_w[2 * p][k], g_w[2 * p + 1][k]);
        cf2[p] = pack2(-g_cf[2 * p], -g_cf[2 * p + 1]);
    }

    // halo-load slots (z-invariant)
    int loff[2]; bool lval[2];
    #pragma unroll
    for (int s = 0; s < 2; s++) {
        int i = tid + s * 256;
        bool ok = (i < ANL);
        int ry = i / (TXX + 2), rx = i % (TXX + 2);
        int gy = y0 + ry - 1, gx = x0 + rx - 1;
        lval[s] = ok && gy >= 0 && gy < HH && gx >= 0 && gx < WW;
        loff[s] = gy * WW + gx;
    }

    const float A = 0.13533528323661270f;

    // stager x-history registers (per owned cell)
    float xmR[2], xcR[2];

    // preload: raw planes zs-1 (slot 3), zs (slot 0), zs+1 (slot 1); aux(zs) slot 0
    #pragma unroll
    for (int s = 0; s < 2; s++) {
        int i = tid + s * 256;
        if (i < ANL) {
            float xv_m = 0, mv_m = 0, xv_0 = 0, mv_0 = 0, xv_p = 0, mv_p = 0;
            if (lval[s]) {
                if (zs > 0) {
                    xv_m = __ldg(Xb + (size_t)(zs - 1) * HW + loff[s]);
                    mv_m = __ldg(Mb + (size_t)(zs - 1) * HW + loff[s]);
                }
                xv_0 = __ldg(Xb + (size_t)zs * HW + loff[s]);
                mv_0 = __ldg(Mb + (size_t)zs * HW + loff[s]);
                xv_p = __ldg(Xb + (size_t)(zs + 1) * HW + loff[s]);
                mv_p = __ldg(Mb + (size_t)(zs + 1) * HW + loff[s]);
            }
            (&raw[3][0][0])[i] = make_float2(xv_m, mv_m);
            (&raw[0][0][0])[i] = make_float2(xv_0, mv_0);
            (&raw[1][0][0])[i] = make_float2(xv_p, mv_p);
            float mp2 = xv_m + xv_p;
            (&aux[0][0][0])[i] = make_float2(fmaf(A, mp2, xv_0), mp2 + xv_0);
            xmR[s] = xv_0;
            xcR[s] = xv_p;
        }
    }

    const u64t ABSM = 0x7FFFFFFF7FFFFFFFull;
    u64t gab2[4] = {0ull, 0ull, 0ull, 0ull};
    float n = 0, m1 = 0, m2 = 0, m3 = 0, m4 = 0;
    float lbp[6] = {0, 0, 0, 0, 0, 0};
    float gs[3] = {0, 0, 0}, gc[3] = {0, 0, 0}, gh[3] = {0, 0, 0};

    for (int z = zs; z < zs + ZCH; z++) {
        __syncthreads();
        // issue LDGs for plane z+2 early (latency hidden by compute below)
        float xn[2] = {0, 0}, mn[2] = {0, 0};
        {
            int zq = z + 2;
            if (zq < DD) {
                const float* Px = Xb + (size_t)zq * HW;
                const float* Pm = Mb + (size_t)zq * HW;
                if (lval[0]) { xn[0] = __ldg(Px + loff[0]); mn[0] = __ldg(Pm + loff[0]); }
                if (lval[1]) { xn[1] = __ldg(Px + loff[1]); mn[1] = __ldg(Pm + loff[1]); }
            }
        }

        const int q0 = (z + 3) & 3, q1 = z & 3, q2 = (z + 1) & 3, az = z & 1;

        // ---- read precomputed (t,s): 9 LDS.64 ----
        float t[9], box;
        {
            float2 a0 = aux[az][ty    ][tx    ];
            float2 a1 = aux[az][ty    ][tx + 1];
            float2 a2 = aux[az][ty    ][tx + 2];
            float2 a3 = aux[az][ty + 1][tx    ];
            float2 a4 = aux[az][ty + 1][tx + 1];
            float2 a5 = aux[az][ty + 1][tx + 2];
            float2 a6 = aux[az][ty + 2][tx    ];
            float2 a7 = aux[az][ty + 2][tx + 1];
            float2 a8 = aux[az][ty + 2][tx + 2];
            t[0] = a0.x; t[1] = a1.x; t[2] = a2.x; t[3] = a3.x; t[4] = a4.x;
            t[5] = a5.x; t[6] = a6.x; t[7] = a7.x; t[8] = a8.x;
            box = a0.y + a1.y; box += a2.y; box += a3.y; box += a4.y;
            box += a5.y; box += a6.y; box += a7.y; box += a8.y;
        }
        float ts0 = t[0] + t[8], ts1 = t[1] + t[7];
        float ts2 = t[2] + t[6], ts3 = t[3] + t[5], ts4 = t[4];
        u64t T0 = pack2(ts0, ts0), T1 = pack2(ts1, ts1), T2 = pack2(ts2, ts2);
        u64t T3 = pack2(ts3, ts3), T4 = pack2(ts4, ts4);
        u64t BX = pack2(box, box);

        u64t g2[4];
        #pragma unroll
        for (int p = 0; p < 4; p++) {
            u64t acc = 0ull;
            fma2(acc, w2[p * 5 + 0], T0);
            fma2(acc, w2[p * 5 + 1], T1);
            fma2(acc, w2[p * 5 + 2], T2);
            fma2(acc, w2[p * 5 + 3], T3);
            fma2(acc, w2[p * 5 + 4], T4);
            fma2(acc, cf2[p], BX);          // - cf * box
            g2[p] = acc;
        }

        // ---- raw neighbors (x,m packed): 7 LDS.64 ----
        float2 rc  = raw[q1][ty + 1][tx + 1];   // c, mc
        float2 rup = raw[q2][ty + 1][tx + 1];   // xup, mzp
        float2 rdn = raw[q0][ty + 1][tx + 1];   // xdn
        float2 ryp = raw[q1][ty + 2][tx + 1];   // xyp, myp
        float2 rym = raw[q1][ty    ][tx + 1];   // xym
        float2 rxp = raw[q1][ty + 1][tx + 2];   // xxp, mxp
        float2 rxm = raw[q1][ty + 1][tx    ];   // xxm
        float c = rc.x, mc = rc.y;
        float xup = rup.x, mzp = rup.y, xdn = rdn.x;
        float xyp = ryp.x, myp = ryp.y, xym = rym.x;
        float xxp = rxp.x, mxp = rxp.y, xxm = rxm.x;

        u64t mcp = pack2(mc, mc);
        #pragma unroll
        for (int p = 0; p < 4; p++) {
            u64t ga = g2[p] & ABSM;         // |gv| packed
            fma2(gab2[p], ga, mcp);
        }

        // moments
        float c2 = c * c;
        n += mc;
        m1 = fmaf(mc, c, m1);
        m2 = fmaf(mc, c2, m2);
        float mcc = mc * c;
        m3 = fmaf(mcc, c2, m3);
        m4 = fmaf(mc * c2, c2, m4);

        // histogram: per-warp smem hist
        if (mc > 0.5f && c >= -1.0f && c <= 1.0f) {
            int bi = (int)floorf(__fmul_rn(__fadd_rn(c, 1.0f), 25.0f));
            bi = min(max(bi, 0), 49);
            atomicAdd(&shHist[warp][bi], 1.0f);
        }

        bool mb = mc > 0.5f;
        if (mb) {
            lbp[0] += (c - xup > 0.0f) ? 1.0f : 0.0f;
            lbp[1] += (c - xdn > 0.0f) ? 1.0f : 0.0f;
            lbp[2] += (c - xyp > 0.0f) ? 1.0f : 0.0f;
            lbp[3] += (c - xym > 0.0f) ? 1.0f : 0.0f;
            lbp[4] += (c - xxp > 0.0f) ? 1.0f : 0.0f;
            lbp[5] += (c - xxm > 0.0f) ? 1.0f : 0.0f;
        }

        {   // GLCM D
            float mp = (mb && mzp > 0.5f) ? 1.0f : 0.0f;
            float d = c - xup, dd = d * d;
            gs[0] += mp;
            gc[0] = fmaf(mp, dd, gc[0]);
            gh[0] = fmaf(mp, __fdividef(1.0f, 1.0f + dd), gh[0]);
        }
        {   // GLCM H
            float mp = (mb && myp > 0.5f) ? 1.0f : 0.0f;
            float d = c - xyp, dd = d * d;
            gs[1] += mp;
            gc[1] = fmaf(mp, dd, gc[1]);
            gh[1] = fmaf(mp, __fdividef(1.0f, 1.0f + dd), gh[1]);
        }
        {   // GLCM W
            float mp = (mb && mxp > 0.5f) ? 1.0f : 0.0f;
            float d = c - xxp, dd = d * d;
            gs[2] += mp;
            gc[2] = fmaf(mp, dd, gc[2]);
            gh[2] = fmaf(mp, __fdividef(1.0f, 1.0f + dd), gh[2]);
        }

        // ---- stage: aux(z+1) from register history; raw(z+2) ----
        {
            int swq = (z + 2) & 3, swa = (z + 1) & 1;
            float2* br = &raw[swq][0][0];
            float2* ba = &aux[swa][0][0];
            // cell 0 (tid < 340 always)
            {
                float mp2 = xmR[0] + xn[0];
                ba[tid] = make_float2(fmaf(A, mp2, xcR[0]), mp2 + xcR[0]);
                br[tid] = make_float2(xn[0], mn[0]);
                xmR[0] = xcR[0]; xcR[0] = xn[0];
            }
            if (tid + 256 < ANL) {
                float mp2 = xmR[1] + xn[1];
                ba[tid + 256] = make_float2(fmaf(A, mp2, xcR[1]), mp2 + xcR[1]);
                br[tid + 256] = make_float2(xn[1], mn[1]);
                xmR[1] = xcR[1]; xcR[1] = xn[1];
            }
        }
    }

    // ---- block reduction ----
    float gabf[8];
    unpack2(gabf[0], gabf[1], gab2[0]);
    unpack2(gabf[2], gabf[3], gab2[1]);
    unpack2(gabf[4], gabf[5], gab2[2]);
    unpack2(gabf[6], gabf[7], gab2[3]);

    float vals[NSCAL];
    vals[0] = n; vals[1] = m1; vals[2] = m2; vals[3] = m3; vals[4] = m4;
    #pragma unroll
    for (int f = 0; f < 8; f++) vals[5 + f] = gabf[f];
    #pragma unroll
    for (int k = 0; k < 6; k++) vals[13 + k] = lbp[k];
    #pragma unroll
    for (int a = 0; a < 3; a++) {
        vals[19 + 3 * a] = gs[a];
        vals[20 + 3 * a] = gc[a];
        vals[21 + 3 * a] = gh[a];
    }

    #pragma unroll
    for (int k = 0; k < NSCAL; k++) {
        float v = vals[k];
        #pragma unroll
        for (int o = 16; o > 0; o >>= 1) v += __shfl_down_sync(0xffffffffu, v, o);
        if (lane == 0) red[k][warp] = v;
    }
    __syncthreads();

    if (tid < NSCAL) {
        double acc = 0.0;
        #pragma unroll
        for (int w = 0; w < 8; w++) acc += (double)red[tid][w];
        atomicAdd(&g_acc[b][tid], acc);
    }
    if (tid >= 64 && tid < 114) {
        int hb = tid - 64;
        float hv = 0.0f;
        #pragma unroll
        for (int w = 0; w < 8; w++) hv += shHist[w][hb];
        atomicAdd(&g_acc[b][NSCAL + hb], (double)hv);
    }
}

// ============================================================
// Finalize: 4 warps, one per batch; bins spread across lanes.
// ============================================================
__global__ void finalize_kernel(float* __restrict__ out) {
    int w = threadIdx.x >> 5, lane = threadIdx.x & 31;
    if (w >= BB) return;
    const double* a = g_acc[w];

    double tot = 0.0;
    for (int k = lane; k < 50; k += 32) tot += a[NSCAL + k];
    #pragma unroll
    for (int o = 16; o > 0; o >>= 1) tot += __shfl_down_sync(0xffffffffu, tot, o);
    tot = __shfl_sync(0xffffffffu, tot, 0);
    tot += 1e-8;

    double ent = 0.0;
    for (int k = lane; k < 50; k += 32) {
        double p = a[NSCAL + k] / tot;
        ent -= p * log(p + 1e-8);
    }
    #pragma unroll
    for (int o = 16; o > 0; o >>= 1) ent += __shfl_down_sync(0xffffffffu, ent, o);

    if (lane == 0) {
        double n = a[0];
        double nn = n > 1.0 ? n : 1.0;
        double mu = a[1] / nn;
        double M2 = a[2] - 2.0 * mu * a[1] + mu * mu * n;
        double nm1 = (n - 1.0) > 1.0 ? (n - 1.0) : 1.0;
        double var = M2 / nm1;
        double sigma = sqrt(var) + 1e-8;
        double M3 = a[3] - 3.0 * mu * a[2] + 3.0 * mu * mu * a[1] - mu * mu * mu * n;
        double M4 = a[4] - 4.0 * mu * a[3] + 6.0 * mu * mu * a[2]
                  - 4.0 * mu * mu * mu * a[1] + mu * mu * mu * mu * n;
        double sg3 = sigma * sigma * sigma;
        double skew = (M3 / sg3) / nn;
        double kurt = (M4 / (sg3 * sigma)) / nn - 3.0;
        double valid = (n >= 10.0) ? 1.0 : 0.0;

        float* o = out + w * 25;
        o[0] = (float)(mu * valid);
        o[1] = (float)(sigma * valid);
        o[2] = (float)(skew * valid);
        o[3] = (float)(kurt * valid);
        o[4] = (float)(ent * valid);
        for (int f = 0; f < 8; f++) o[5 + f] = (float)(a[5 + f] / nn);
        for (int k = 0; k < 6; k++) o[13 + k] = (float)(a[13 + k] / nn);
        for (int ax = 0; ax < 3; ax++) {
            double s = a[19 + 3 * ax];
            double ss = s > 1.0 ? s : 1.0;
            double ok = (s >= 4.0) ? 1.0 : 0.0;
            o[19 + 2 * ax]     = (float)((a[20 + 3 * ax] / ss) * ok);
            o[19 + 2 * ax + 1] = (float)((a[21 + 3 * ax] / ss) * ok);
        }
    }
}

extern "C" void kernel_launch(void* const* d_in, const int* in_sizes, int n_in,
                              void* d_out, int out_size) {
    const float* x  = (const float*)d_in[0];
    const float* m  = (const float*)d_in[1];
    const float* gf = (const float*)d_in[2];

    prep_kernel<<<1, 352>>>(gf);

    dim3 grid(WW / TXX, HH / TYY, BB * 4);  // (5, 20, 16) = 1600 CTAs
    dim3 blk(TXX, TYY);
    fused_kernel<<<grid, blk>>>(x, m);

    finalize_kernel<<<1, 128>>>((float*)d_out);
}

// round 7
// speedup vs baseline: 3.6384x; 1.2006x over previous
#include <cuda_runtime.h>
#include <math.h>

#define BB 4
#define DD 96
#define HH 160
#define WW 160
#define HW (HH*WW)
#define NSCAL 28
#define NACC  78   // 28 scalars + 50 histogram bins

__device__ double g_acc[BB][NACC];
__device__ float g_w[8][5];
__device__ float g_cf[8];

typedef unsigned long long u64t;
__device__ __forceinline__ u64t pack2(float lo, float hi) {
    u64t r; asm("mov.b64 %0,{%1,%2};" : "=l"(r) : "f"(lo), "f"(hi)); return r;
}
__device__ __forceinline__ void unpack2(float& lo, float& hi, u64t v) {
    asm("mov.b64 {%0,%1},%2;" : "=f"(lo), "=f"(hi) : "l"(v));
}
__device__ __forceinline__ void fma2(u64t& d, u64t a, u64t b) {
    asm("fma.rn.f32x2 %0,%1,%2,%0;" : "+l"(d) : "l"(a), "l"(b));
}

// ============================================================
// prep: zero accumulators + derive weights (see R5 derivation).
// ============================================================
__global__ void prep_kernel(const float* __restrict__ gf) {
    int t = threadIdx.x;
    if (t < BB * NACC) ((double*)g_acc)[t] = 0.0;
    if (t >= 320 && t < 328) {
        int f = t - 320;
        const float A = 0.13533528323661270f;  // exp(-2)
        float u[9], cacc = 0.0f;
        #pragma unroll
        for (int j = 0; j < 9; j++) {
            float F1 = gf[f * 27 + 9 + j];
            float F0 = gf[f * 27 + j];
            u[j] = (F1 - F0) * (1.0f / (1.0f - A));
            cacc += (u[j] - F1);
        }
        g_cf[f] = cacc * (1.0f / 9.0f);
        g_w[f][0] = (u[0] + u[8]) * 0.5f;
        g_w[f][1] = (u[1] + u[7]) * 0.5f;
        g_w[f][2] = (u[2] + u[6]) * 0.5f;
        g_w[f][3] = (u[3] + u[5]) * 0.5f;
        g_w[f][4] = u[4];
    }
}

// ============================================================
// Fused kernel, 2 voxels/thread stacked in y (tile 32x16).
// Split x/m smem arrays; aux(t,s) float2 ring; 1 sync/z.
// ============================================================
#define TXX 32
#define TYV 16            // voxel rows per tile
#define HR  (TYV + 2)     // 18 halo rows
#define HC  (TXX + 2)     // 34 halo cols
#define ANL (HR * HC)     // 612
#define ZCH 24

__global__ __launch_bounds__(256)
void fused_kernel(const float* __restrict__ X, const float* __restrict__ M) {
    __shared__ float xsh[4][HR][HC];
    __shared__ float msk[4][HR][HC];
    __shared__ float2 aux[2][HR][HC];      // (t, s)
    __shared__ float shHist[8][50];
    __shared__ float red[NSCAL][8];

    const int tx = threadIdx.x, ty = threadIdx.y;     // ty in 0..7
    const int tid = ty * TXX + tx;
    const int warp = tid >> 5, lane = tid & 31;
    const int x0 = blockIdx.x * TXX, y0 = blockIdx.y * TYV;
    const int b = blockIdx.z >> 2;
    const int zs = (blockIdx.z & 3) * ZCH;
    const float* Xb = X + (size_t)b * DD * HW;
    const float* Mb = M + (size_t)b * DD * HW;

    for (int i = tid; i < 400; i += 256) ((float*)shHist)[i] = 0.0f;

    // packed weights: pair filters (2p, 2p+1)
    u64t w2[20], cf2[4];
    #pragma unroll
    for (int p = 0; p < 4; p++) {
        #pragma unroll
        for (int k = 0; k < 5; k++)
            w2[p * 5 + k] = pack2(g_w[2 * p][k], g_w[2 * p + 1][k]);
        cf2[p] = pack2(-g_cf[2 * p], -g_cf[2 * p + 1]);
    }

    // halo-load slots (3 segments, z-invariant)
    int loff[3]; bool lval[3];
    #pragma unroll
    for (int s = 0; s < 3; s++) {
        int i = tid + s * 256;
        bool ok = (i < ANL);
        int ry = ok ? i / HC : 0, rx = ok ? i % HC : 0;
        int gy = y0 + ry - 1, gx = x0 + rx - 1;
        lval[s] = ok && gy >= 0 && gy < HH && gx >= 0 && gx < WW;
        loff[s] = gy * WW + gx;
    }

    const float A = 0.13533528323661270f;
    float xmR[3], xcR[3];

    // preload raw planes zs-1 (slot 3), zs (0), zs+1 (1); aux(zs) slot 0
    #pragma unroll
    for (int s = 0; s < 3; s++) {
        int i = tid + s * 256;
        if (i < ANL) {
            float xv_m = 0, mv_m = 0, xv_0 = 0, mv_0 = 0, xv_p = 0, mv_p = 0;
            if (lval[s]) {
                if (zs > 0) {
                    xv_m = __ldg(Xb + (size_t)(zs - 1) * HW + loff[s]);
                    mv_m = __ldg(Mb + (size_t)(zs - 1) * HW + loff[s]);
                }
                xv_0 = __ldg(Xb + (size_t)zs * HW + loff[s]);
                mv_0 = __ldg(Mb + (size_t)zs * HW + loff[s]);
                xv_p = __ldg(Xb + (size_t)(zs + 1) * HW + loff[s]);
                mv_p = __ldg(Mb + (size_t)(zs + 1) * HW + loff[s]);
            }
            (&xsh[3][0][0])[i] = xv_m;  (&msk[3][0][0])[i] = mv_m;
            (&xsh[0][0][0])[i] = xv_0;  (&msk[0][0][0])[i] = mv_0;
            (&xsh[1][0][0])[i] = xv_p;  (&msk[1][0][0])[i] = mv_p;
            float mp2 = xv_m + xv_p;
            (&aux[0][0][0])[i] = make_float2(fmaf(A, mp2, xv_0), mp2 + xv_0);
            xmR[s] = xv_0;
            xcR[s] = xv_p;
        }
    }

    const u64t ABSM = 0x7FFFFFFF7FFFFFFFull;
    u64t gab2[4] = {0ull, 0ull, 0ull, 0ull};
    float n = 0, m1 = 0, m2 = 0, m3 = 0, m4 = 0;
    float lbp[6] = {0, 0, 0, 0, 0, 0};
    float gs[3] = {0, 0, 0}, gc[3] = {0, 0, 0}, gh[3] = {0, 0, 0};

    const int vy0 = 2 * ty + 1, vy1 = 2 * ty + 2, txc = tx + 1;

    for (int z = zs; z < zs + ZCH; z++) {
        __syncthreads();
        // issue LDGs for plane z+2 early
        float xn[3] = {0, 0, 0}, mn[3] = {0, 0, 0};
        {
            int zq = z + 2;
            if (zq < DD) {
                const float* Px = Xb + (size_t)zq * HW;
                const float* Pm = Mb + (size_t)zq * HW;
                #pragma unroll
                for (int s = 0; s < 3; s++)
                    if (lval[s]) { xn[s] = __ldg(Px + loff[s]); mn[s] = __ldg(Pm + loff[s]); }
            }
        }

        const int q0 = (z + 3) & 3, q1 = z & 3, q2 = (z + 1) & 3, az = z & 1;

        // ---- aux window: 4 rows x 3 cols (12 LDS.64) covers both voxels ----
        float t[4][3], rowS[4];
        #pragma unroll
        for (int r = 0; r < 4; r++) {
            float2 a0 = aux[az][2 * ty + r][tx    ];
            float2 a1 = aux[az][2 * ty + r][tx + 1];
            float2 a2 = aux[az][2 * ty + r][tx + 2];
            t[r][0] = a0.x; t[r][1] = a1.x; t[r][2] = a2.x;
            rowS[r] = a0.y + a1.y + a2.y;
        }

        // ---- raw reads (split x / m) ----
        float xv0 = xsh[q1][vy0 - 1][txc];
        float xv1 = xsh[q1][vy0    ][txc];
        float xv2 = xsh[q1][vy1    ][txc];
        float xv3 = xsh[q1][vy1 + 1][txc];
        float xxm0 = xsh[q1][vy0][tx], xxp0 = xsh[q1][vy0][tx + 2];
        float xxm1 = xsh[q1][vy1][tx], xxp1 = xsh[q1][vy1][tx + 2];
        float xup0 = xsh[q2][vy0][txc], xup1 = xsh[q2][vy1][txc];
        float xdn0 = xsh[q0][vy0][txc], xdn1 = xsh[q0][vy1][txc];
        float mc0 = msk[q1][vy0][txc], mc1 = msk[q1][vy1][txc];
        float myp1 = msk[q1][vy1 + 1][txc];
        float mxp0 = msk[q1][vy0][tx + 2], mxp1 = msk[q1][vy1][tx + 2];
        float mzp0 = msk[q2][vy0][txc], mzp1 = msk[q2][vy1][txc];

        // ---- per-voxel gabor matvec + stats (macro over row base) ----
        #define DO_VOXEL(R, CC, MC, XUP, XDN, XYP, XYM, XXP, XXM, MZP, MYP, MXP)          \
        {                                                                                  \
            float C  = t[R][0] + t[R + 2][2];                                              \
            float CA = t[R][2] + t[R + 2][0];                                              \
            float Ey = t[R][1] + t[R + 2][1];                                              \
            float Ex = t[R + 1][0] + t[R + 1][2];                                          \
            float ct = t[R + 1][1];                                                        \
            float box = rowS[R] + rowS[R + 1] + rowS[R + 2];                               \
            u64t T0 = pack2(C, C),  T1 = pack2(Ey, Ey), T2 = pack2(CA, CA);                \
            u64t T3 = pack2(Ex, Ex), T4 = pack2(ct, ct), BX = pack2(box, box);             \
            u64t mcp = pack2(MC, MC);                                                      \
            _Pragma("unroll")                                                              \
            for (int p = 0; p < 4; p++) {                                                  \
                u64t acc = 0ull;                                                           \
                fma2(acc, w2[p * 5 + 0], T0);                                              \
                fma2(acc, w2[p * 5 + 1], T1);                                              \
                fma2(acc, w2[p * 5 + 2], T2);                                              \
                fma2(acc, w2[p * 5 + 3], T3);                                              \
                fma2(acc, w2[p * 5 + 4], T4);                                              \
                fma2(acc, cf2[p], BX);                                                     \
                acc &= ABSM;                                                               \
                fma2(gab2[p], acc, mcp);                                                   \
            }                                                                              \
            float c2 = CC * CC;                                                            \
            n += MC;                                                                       \
            m1 = fmaf(MC, CC, m1);                                                         \
            m2 = fmaf(MC, c2, m2);                                                         \
            float mcc = MC * CC;                                                           \
            m3 = fmaf(mcc, c2, m3);                                                        \
            m4 = fmaf(MC * c2, c2, m4);                                                    \
            if (MC > 0.5f && CC >= -1.0f && CC <= 1.0f) {                                  \
                int bi = (int)floorf(__fmul_rn(__fadd_rn(CC, 1.0f), 25.0f));               \
                bi = min(max(bi, 0), 49);                                                  \
                atomicAdd(&shHist[warp][bi], 1.0f);                                        \
            }                                                                              \
            bool mb = MC > 0.5f;                                                           \
            if (mb) {                                                                      \
                lbp[0] += (CC - XUP > 0.0f) ? 1.0f : 0.0f;                                 \
                lbp[1] += (CC - XDN > 0.0f) ? 1.0f : 0.0f;                                 \
                lbp[2] += (CC - XYP > 0.0f) ? 1.0f : 0.0f;                                 \
                lbp[3] += (CC - XYM > 0.0f) ? 1.0f : 0.0f;                                 \
                lbp[4] += (CC - XXP > 0.0f) ? 1.0f : 0.0f;                                 \
                lbp[5] += (CC - XXM > 0.0f) ? 1.0f : 0.0f;                                 \
            }                                                                              \
            {                                                                              \
                float mp = (mb && MZP > 0.5f) ? 1.0f : 0.0f;                               \
                float d = CC - XUP, dd = d * d;                                            \
                gs[0] += mp;                                                               \
                gc[0] = fmaf(mp, dd, gc[0]);                                               \
                gh[0] = fmaf(mp, __fdividef(1.0f, 1.0f + dd), gh[0]);                      \
            }                                                                              \
            {                                                                              \
                float mp = (mb && MYP > 0.5f) ? 1.0f : 0.0f;                               \
                float d = CC - XYP, dd = d * d;                                            \
                gs[1] += mp;                                                               \
                gc[1] = fmaf(mp, dd, gc[1]);                                               \
                gh[1] = fmaf(mp, __fdividef(1.0f, 1.0f + dd), gh[1]);                      \
            }                                                                              \
            {                                                                              \
                float mp = (mb && MXP > 0.5f) ? 1.0f : 0.0f;                               \
                float d = CC - XXP, dd = d * d;                                            \
                gs[2] += mp;                                                               \
                gc[2] = fmaf(mp, dd, gc[2]);                                               \
                gh[2] = fmaf(mp, __fdividef(1.0f, 1.0f + dd), gh[2]);                      \
            }                                                                              \
        }

        DO_VOXEL(0, xv1, mc0, xup0, xdn0, xv2, xv0, xxp0, xxm0, mzp0, mc1,  mxp0)
        DO_VOXEL(1, xv2, mc1, xup1, xdn1, xv3, xv1, xxp1, xxm1, mzp1, myp1, mxp1)
        #undef DO_VOXEL

        // ---- stage: aux(z+1) from register history; raw(z+2) ----
        {
            int swq = (z + 2) & 3, swa = (z + 1) & 1;
            float* bx = &xsh[swq][0][0];
            float* bm = &msk[swq][0][0];
            float2* ba = &aux[swa][0][0];
            #pragma unroll
            for (int s = 0; s < 3; s++) {
                int i = tid + s * 256;
                if (s < 2 || i < ANL) {
                    float mp2 = xmR[s] + xn[s];
                    ba[i] = make_float2(fmaf(A, mp2, xcR[s]), mp2 + xcR[s]);
                    bx[i] = xn[s];
                    bm[i] = mn[s];
                    xmR[s] = xcR[s]; xcR[s] = xn[s];
                }
            }
        }
    }

    // ---- block reduction ----
    float gabf[8];
    unpack2(gabf[0], gabf[1], gab2[0]);
    unpack2(gabf[2], gabf[3], gab2[1]);
    unpack2(gabf[4], gabf[5], gab2[2]);
    unpack2(gabf[6], gabf[7], gab2[3]);

    float vals[NSCAL];
    vals[0] = n; vals[1] = m1; vals[2] = m2; vals[3] = m3; vals[4] = m4;
    #pragma unroll
    for (int f = 0; f < 8; f++) vals[5 + f] = gabf[f];
    #pragma unroll
    for (int k = 0; k < 6; k++) vals[13 + k] = lbp[k];
    #pragma unroll
    for (int a = 0; a < 3; a++) {
        vals[19 + 3 * a] = gs[a];
        vals[20 + 3 * a] = gc[a];
        vals[21 + 3 * a] = gh[a];
    }

    #pragma unroll
    for (int k = 0; k < NSCAL; k++) {
        float v = vals[k];
        #pragma unroll
        for (int o = 16; o > 0; o >>= 1) v += __shfl_down_sync(0xffffffffu, v, o);
        if (lane == 0) red[k][warp] = v;
    }
    __syncthreads();

    if (tid < NSCAL) {
        double acc = 0.0;
        #pragma unroll
        for (int w = 0; w < 8; w++) acc += (double)red[tid][w];
        atomicAdd(&g_acc[b][tid], acc);
    }
    if (tid >= 64 && tid < 114) {
        int hb = tid - 64;
        float hv = 0.0f;
        #pragma unroll
        for (int w = 0; w < 8; w++) hv += shHist[w][hb];
        atomicAdd(&g_acc[b][NSCAL + hb], (double)hv);
    }
}

// ============================================================
// Finalize: 4 warps, one per batch; bins spread across lanes.
// ============================================================
__global__ void finalize_kernel(float* __restrict__ out) {
    int w = threadIdx.x >> 5, lane = threadIdx.x & 31;
    if (w >= BB) return;
    const double* a = g_acc[w];

    double tot = 0.0;
    for (int k = lane; k < 50; k += 32) tot += a[NSCAL + k];
    #pragma unroll
    for (int o = 16; o > 0; o >>= 1) tot += __shfl_down_sync(0xffffffffu, tot, o);
    tot = __shfl_sync(0xffffffffu, tot, 0);
    tot += 1e-8;

    double ent = 0.0;
    for (int k = lane; k < 50; k += 32) {
        double p = a[NSCAL + k] / tot;
        ent -= p * log(p + 1e-8);
    }
    #pragma unroll
    for (int o = 16; o > 0; o >>= 1) ent += __shfl_down_sync(0xffffffffu, ent, o);

    if (lane == 0) {
        double n = a[0];
        double nn = n > 1.0 ? n : 1.0;
        double mu = a[1] / nn;
        double M2 = a[2] - 2.0 * mu * a[1] + mu * mu * n;
        double nm1 = (n - 1.0) > 1.0 ? (n - 1.0) : 1.0;
        double var = M2 / nm1;
        double sigma = sqrt(var) + 1e-8;
        double M3 = a[3] - 3.0 * mu * a[2] + 3.0 * mu * mu * a[1] - mu * mu * mu * n;
        double M4 = a[4] - 4.0 * mu * a[3] + 6.0 * mu * mu * a[2]
                  - 4.0 * mu * mu * mu * a[1] + mu * mu * mu * mu * n;
        double sg3 = sigma * sigma * sigma;
        double skew = (M3 / sg3) / nn;
        double kurt = (M4 / (sg3 * sigma)) / nn - 3.0;
        double valid = (n >= 10.0) ? 1.0 : 0.0;

        float* o = out + w * 25;
        o[0] = (float)(mu * valid);
        o[1] = (float)(sigma * valid);
        o[2] = (float)(skew * valid);
        o[3] = (float)(kurt * valid);
        o[4] = (float)(ent * valid);
        for (int f = 0; f < 8; f++) o[5 + f] = (float)(a[5 + f] / nn);
        for (int k = 0; k < 6; k++) o[13 + k] = (float)(a[13 + k] / nn);
        for (int ax = 0; ax < 3; ax++) {
            double s = a[19 + 3 * ax];
            double ss = s > 1.0 ? s : 1.0;
            double ok = (s >= 4.0) ? 1.0 : 0.0;
            o[19 + 2 * ax]     = (float)((a[20 + 3 * ax] / ss) * ok);
            o[19 + 2 * ax + 1] = (float)((a[21 + 3 * ax] / ss) * ok);
        }
    }
}

extern "C" void kernel_launch(void* const* d_in, const int* in_sizes, int n_in,
                              void* d_out, int out_size) {
    const float* x  = (const float*)d_in[0];
    const float* m  = (const float*)d_in[1];
    const float* gf = (const float*)d_in[2];

    prep_kernel<<<1, 352>>>(gf);

    dim3 grid(WW / TXX, HH / TYV, BB * 4);  // (5, 10, 16) = 800 CTAs
    dim3 blk(TXX, 8);
    fused_kernel<<<grid, blk>>>(x, m);

    finalize_kernel<<<1, 128>>>((float*)d_out);
}

// round 8
// speedup vs baseline: 3.9294x; 1.0800x over previous
#include <cuda_runtime.h>
#include <math.h>

#define BB 4
#define DD 96
#define HH 160
#define WW 160
#define HW (HH*WW)
#define NSCAL 28
#define NACC  78   // 28 scalars + 50 histogram bins

__device__ double g_acc[BB][NACC];
__device__ float g_w[8][5];
__device__ float g_cf[8];

typedef unsigned long long u64t;
__device__ __forceinline__ u64t pack2(float lo, float hi) {
    u64t r; asm("mov.b64 %0,{%1,%2};" : "=l"(r) : "f"(lo), "f"(hi)); return r;
}
__device__ __forceinline__ void unpack2(float& lo, float& hi, u64t v) {
    asm("mov.b64 {%0,%1},%2;" : "=f"(lo), "=f"(hi) : "l"(v));
}
__device__ __forceinline__ void fma2(u64t& d, u64t a, u64t b) {
    asm("fma.rn.f32x2 %0,%1,%2,%0;" : "+l"(d) : "l"(a), "l"(b));
}

// ============================================================
// prep: zero accumulators + derive weights (see R5 derivation).
// ============================================================
__global__ void prep_kernel(const float* __restrict__ gf) {
    int t = threadIdx.x;
    if (t < BB * NACC) ((double*)g_acc)[t] = 0.0;
    if (t >= 320 && t < 328) {
        int f = t - 320;
        const float A = 0.13533528323661270f;  // exp(-2)
        float u[9], cacc = 0.0f;
        #pragma unroll
        for (int j = 0; j < 9; j++) {
            float F1 = gf[f * 27 + 9 + j];
            float F0 = gf[f * 27 + j];
            u[j] = (F1 - F0) * (1.0f / (1.0f - A));
            cacc += (u[j] - F1);
        }
        g_cf[f] = cacc * (1.0f / 9.0f);
        g_w[f][0] = (u[0] + u[8]) * 0.5f;
        g_w[f][1] = (u[1] + u[7]) * 0.5f;
        g_w[f][2] = (u[2] + u[6]) * 0.5f;
        g_w[f][3] = (u[3] + u[5]) * 0.5f;
        g_w[f][4] = u[4];
    }
}

// ============================================================
// Fused kernel, 2 voxels/thread stacked in y (tile 32x16).
// Per-THREAD u16 smem histogram (no atomics); center-column
// register rotation along z.
// ============================================================
#define TXX 32
#define TYV 16            // voxel rows per tile
#define HR  (TYV + 2)     // 18 halo rows
#define HC  (TXX + 2)     // 34 halo cols
#define ANL (HR * HC)     // 612
#define ZCH 24
#define HPITCH 258        // u16 row pitch (256 threads + 2 pad)

__global__ __launch_bounds__(256)
void fused_kernel(const float* __restrict__ X, const float* __restrict__ M) {
    __shared__ float xsh[4][HR][HC];
    __shared__ float msk[4][HR][HC];
    __shared__ float2 aux[2][HR][HC];            // (t, s)
    __shared__ unsigned short h16[50 * HPITCH];  // per-thread histogram
    __shared__ float red[NSCAL][8];

    const int tx = threadIdx.x, ty = threadIdx.y;     // ty in 0..7
    const int tid = ty * TXX + tx;
    const int warp = tid >> 5, lane = tid & 31;
    const int x0 = blockIdx.x * TXX, y0 = blockIdx.y * TYV;
    const int b = blockIdx.z >> 2;
    const int zs = (blockIdx.z & 3) * ZCH;
    const float* Xb = X + (size_t)b * DD * HW;
    const float* Mb = M + (size_t)b * DD * HW;

    // zero per-thread histogram (u32 strided)
    {
        unsigned* h32 = (unsigned*)h16;
        #pragma unroll
        for (int i = tid; i < 50 * HPITCH / 2; i += 256) h32[i] = 0u;
    }

    // packed weights: pair filters (2p, 2p+1)
    u64t w2[20], cf2[4];
    #pragma unroll
    for (int p = 0; p < 4; p++) {
        #pragma unroll
        for (int k = 0; k < 5; k++)
            w2[p * 5 + k] = pack2(g_w[2 * p][k], g_w[2 * p + 1][k]);
        cf2[p] = pack2(-g_cf[2 * p], -g_cf[2 * p + 1]);
    }

    // halo-load slots (3 segments, z-invariant)
    int loff[3]; bool lval[3];
    #pragma unroll
    for (int s = 0; s < 3; s++) {
        int i = tid + s * 256;
        bool ok = (i < ANL);
        int ry = ok ? i / HC : 0, rx = ok ? i % HC : 0;
        int gy = y0 + ry - 1, gx = x0 + rx - 1;
        lval[s] = ok && gy >= 0 && gy < HH && gx >= 0 && gx < WW;
        loff[s] = gy * WW + gx;
    }

    const float A = 0.13533528323661270f;
    float xmR[3], xcR[3];

    // preload raw planes zs-1 (slot 3), zs (0), zs+1 (1); aux(zs) slot 0
    #pragma unroll
    for (int s = 0; s < 3; s++) {
        int i = tid + s * 256;
        if (i < ANL) {
            float xv_m = 0, mv_m = 0, xv_0 = 0, mv_0 = 0, xv_p = 0, mv_p = 0;
            if (lval[s]) {
                if (zs > 0) {
                    xv_m = __ldg(Xb + (size_t)(zs - 1) * HW + loff[s]);
                    mv_m = __ldg(Mb + (size_t)(zs - 1) * HW + loff[s]);
                }
                xv_0 = __ldg(Xb + (size_t)zs * HW + loff[s]);
                mv_0 = __ldg(Mb + (size_t)zs * HW + loff[s]);
                xv_p = __ldg(Xb + (size_t)(zs + 1) * HW + loff[s]);
                mv_p = __ldg(Mb + (size_t)(zs + 1) * HW + loff[s]);
            }
            (&xsh[3][0][0])[i] = xv_m;  (&msk[3][0][0])[i] = mv_m;
            (&xsh[0][0][0])[i] = xv_0;  (&msk[0][0][0])[i] = mv_0;
            (&xsh[1][0][0])[i] = xv_p;  (&msk[1][0][0])[i] = mv_p;
            float mp2 = xv_m + xv_p;
            (&aux[0][0][0])[i] = make_float2(fmaf(A, mp2, xv_0), mp2 + xv_0);
            xmR[s] = xv_0;
            xcR[s] = xv_p;
        }
    }

    const u64t ABSM = 0x7FFFFFFF7FFFFFFFull;
    u64t gab2[4] = {0ull, 0ull, 0ull, 0ull};
    float n = 0, m1 = 0, m2 = 0, m3 = 0, m4 = 0;
    float lbp[6] = {0, 0, 0, 0, 0, 0};
    float gs[3] = {0, 0, 0}, gc[3] = {0, 0, 0}, gh[3] = {0, 0, 0};

    const int vy0 = 2 * ty + 1, vy1 = 2 * ty + 2, txc = tx + 1;

    __syncthreads();   // histogram zero + preload visible

    // center-column register rotation state (c, xdn, mc per voxel)
    float cc0 = xsh[0][vy0][txc], cc1 = xsh[0][vy1][txc];
    float cd0 = xsh[3][vy0][txc], cd1 = xsh[3][vy1][txc];
    float cm0 = msk[0][vy0][txc], cm1 = msk[0][vy1][txc];

    for (int z = zs; z < zs + ZCH; z++) {
        // issue LDGs for plane z+2 early
        float xn[3] = {0, 0, 0}, mn[3] = {0, 0, 0};
        {
            int zq = z + 2;
            if (zq < DD) {
                const float* Px = Xb + (size_t)zq * HW;
                const float* Pm = Mb + (size_t)zq * HW;
                #pragma unroll
                for (int s = 0; s < 3; s++)
                    if (lval[s]) { xn[s] = __ldg(Px + loff[s]); mn[s] = __ldg(Pm + loff[s]); }
            }
        }

        const int q1 = z & 3, q2 = (z + 1) & 3, az = z & 1;

        // ---- aux window: 4 rows x 3 cols (12 LDS.64) covers both voxels ----
        float t[4][3], rowS[4];
        #pragma unroll
        for (int r = 0; r < 4; r++) {
            float2 a0 = aux[az][2 * ty + r][tx    ];
            float2 a1 = aux[az][2 * ty + r][tx + 1];
            float2 a2 = aux[az][2 * ty + r][tx + 2];
            t[r][0] = a0.x; t[r][1] = a1.x; t[r][2] = a2.x;
            rowS[r] = a0.y + a1.y + a2.y;
        }

        // ---- raw reads (split x / m); center column from registers ----
        float xv0 = xsh[q1][vy0 - 1][txc];
        float xv1 = cc0;
        float xv2 = cc1;
        float xv3 = xsh[q1][vy1 + 1][txc];
        float xxm0 = xsh[q1][vy0][tx], xxp0 = xsh[q1][vy0][tx + 2];
        float xxm1 = xsh[q1][vy1][tx], xxp1 = xsh[q1][vy1][tx + 2];
        float xup0 = xsh[q2][vy0][txc], xup1 = xsh[q2][vy1][txc];
        float xdn0 = cd0, xdn1 = cd1;
        float mc0 = cm0, mc1 = cm1;
        float myp1 = msk[q1][vy1 + 1][txc];
        float mxp0 = msk[q1][vy0][tx + 2], mxp1 = msk[q1][vy1][tx + 2];
        float mzp0 = msk[q2][vy0][txc], mzp1 = msk[q2][vy1][txc];

        #define DO_VOXEL(R, CC, MC, XUP, XDN, XYP, XYM, XXP, XXM, MZP, MYP, MXP)          \
        {                                                                                  \
            float C  = t[R][0] + t[R + 2][2];                                              \
            float CA = t[R][2] + t[R + 2][0];                                              \
            float Ey = t[R][1] + t[R + 2][1];                                              \
            float Ex = t[R + 1][0] + t[R + 1][2];                                          \
            float ct = t[R + 1][1];                                                        \
            float box = rowS[R] + rowS[R + 1] + rowS[R + 2];                               \
            u64t T0 = pack2(C, C),  T1 = pack2(Ey, Ey), T2 = pack2(CA, CA);                \
            u64t T3 = pack2(Ex, Ex), T4 = pack2(ct, ct), BX = pack2(box, box);             \
            u64t mcp = pack2(MC, MC);                                                      \
            _Pragma("unroll")                                                              \
            for (int p = 0; p < 4; p++) {                                                  \
                u64t acc = 0ull;                                                           \
                fma2(acc, w2[p * 5 + 0], T0);                                              \
                fma2(acc, w2[p * 5 + 1], T1);                                              \
                fma2(acc, w2[p * 5 + 2], T2);                                              \
                fma2(acc, w2[p * 5 + 3], T3);                                              \
                fma2(acc, w2[p * 5 + 4], T4);                                              \
                fma2(acc, cf2[p], BX);                                                     \
                acc &= ABSM;                                                               \
                fma2(gab2[p], acc, mcp);                                                   \
            }                                                                              \
            float c2 = CC * CC;                                                            \
            n += MC;                                                                       \
            m1 = fmaf(MC, CC, m1);                                                         \
            m2 = fmaf(MC, c2, m2);                                                         \
            float mcc = MC * CC;                                                           \
            m3 = fmaf(mcc, c2, m3);                                                        \
            m4 = fmaf(MC * c2, c2, m4);                                                    \
            if (MC > 0.5f && CC >= -1.0f && CC <= 1.0f) {                                  \
                int bi = (int)floorf(__fmul_rn(__fadd_rn(CC, 1.0f), 25.0f));               \
                bi = min(max(bi, 0), 49);                                                  \
                h16[bi * HPITCH + tid] += 1;                                               \
            }                                                                              \
            bool mb = MC > 0.5f;                                                           \
            if (mb) {                                                                      \
                lbp[0] += (CC - XUP > 0.0f) ? 1.0f : 0.0f;                                 \
                lbp[1] += (CC - XDN > 0.0f) ? 1.0f : 0.0f;                                 \
                lbp[2] += (CC - XYP > 0.0f) ? 1.0f : 0.0f;                                 \
                lbp[3] += (CC - XYM > 0.0f) ? 1.0f : 0.0f;                                 \
                lbp[4] += (CC - XXP > 0.0f) ? 1.0f : 0.0f;                                 \
                lbp[5] += (CC - XXM > 0.0f) ? 1.0f : 0.0f;                                 \
            }                                                                              \
            {                                                                              \
                float mp = (mb && MZP > 0.5f) ? 1.0f : 0.0f;                               \
                float d = CC - XUP, dd = d * d;                                            \
                gs[0] += mp;                                                               \
                gc[0] = fmaf(mp, dd, gc[0]);                                               \
                gh[0] = fmaf(mp, __fdividef(1.0f, 1.0f + dd), gh[0]);                      \
            }                                                                              \
            {                                                                              \
                float mp = (mb && MYP > 0.5f) ? 1.0f : 0.0f;                               \
                float d = CC - XYP, dd = d * d;                                            \
                gs[1] += mp;                                                               \
                gc[1] = fmaf(mp, dd, gc[1]);                                               \
                gh[1] = fmaf(mp, __fdividef(1.0f, 1.0f + dd), gh[1]);                      \
            }                                                                              \
            {                                                                              \
                float mp = (mb && MXP > 0.5f) ? 1.0f : 0.0f;                               \
                float d = CC - XXP, dd = d * d;                                            \
                gs[2] += mp;                                                               \
                gc[2] = fmaf(mp, dd, gc[2]);                                               \
                gh[2] = fmaf(mp, __fdividef(1.0f, 1.0f + dd), gh[2]);                      \
            }                                                                              \
        }

        DO_VOXEL(0, xv1, mc0, xup0, xdn0, xv2, xv0, xxp0, xxm0, mzp0, mc1,  mxp0)
        DO_VOXEL(1, xv2, mc1, xup1, xdn1, xv3, xv1, xxp1, xxm1, mzp1, myp1, mxp1)
        #undef DO_VOXEL

        // rotate center-column registers
        cd0 = cc0; cd1 = cc1;
        cc0 = xup0; cc1 = xup1;
        cm0 = mzp0; cm1 = mzp1;

        __syncthreads();   // all reads of current plane done before staging

        // ---- stage: aux(z+1) from register history; raw(z+2) ----
        {
            int swq = (z + 2) & 3, swa = (z + 1) & 1;
            float* bx = &xsh[swq][0][0];
            float* bm = &msk[swq][0][0];
            float2* ba = &aux[swa][0][0];
            #pragma unroll
            for (int s = 0; s < 3; s++) {
                int i = tid + s * 256;
                if (s < 2 || i < ANL) {
                    float mp2 = xmR[s] + xn[s];
                    ba[i] = make_float2(fmaf(A, mp2, xcR[s]), mp2 + xcR[s]);
                    bx[i] = xn[s];
                    bm[i] = mn[s];
                    xmR[s] = xcR[s]; xcR[s] = xn[s];
                }
            }
        }
        __syncthreads();   // staging visible before next-plane reads
    }

    // ---- histogram reduction: warp w handles bins w, w+8, ... ----
    for (int bbin = warp; bbin < 50; bbin += 8) {
        const unsigned* p = (const unsigned*)&h16[bbin * HPITCH];
        unsigned s = 0;
        #pragma unroll
        for (int k = 0; k < 4; k++) {
            unsigned v = p[lane * 4 + k];
            s += (v & 0xffffu) + (v >> 16);
        }
        #pragma unroll
        for (int o = 16; o > 0; o >>= 1) s += __shfl_down_sync(0xffffffffu, s, o);
        if (lane == 0) atomicAdd(&g_acc[b][NSCAL + bbin], (double)s);
    }

    // ---- block reduction of 28 scalars ----
    float gabf[8];
    unpack2(gabf[0], gabf[1], gab2[0]);
    unpack2(gabf[2], gabf[3], gab2[1]);
    unpack2(gabf[4], gabf[5], gab2[2]);
    unpack2(gabf[6], gabf[7], gab2[3]);

    float vals[NSCAL];
    vals[0] = n; vals[1] = m1; vals[2] = m2; vals[3] = m3; vals[4] = m4;
    #pragma unroll
    for (int f = 0; f < 8; f++) vals[5 + f] = gabf[f];
    #pragma unroll
    for (int k = 0; k < 6; k++) vals[13 + k] = lbp[k];
    #pragma unroll
    for (int a = 0; a < 3; a++) {
        vals[19 + 3 * a] = gs[a];
        vals[20 + 3 * a] = gc[a];
        vals[21 + 3 * a] = gh[a];
    }

    #pragma unroll
    for (int k = 0; k < NSCAL; k++) {
        float v = vals[k];
        #pragma unroll
        for (int o = 16; o > 0; o >>= 1) v += __shfl_down_sync(0xffffffffu, v, o);
        if (lane == 0) red[k][warp] = v;
    }
    __syncthreads();

    if (tid < NSCAL) {
        double acc = 0.0;
        #pragma unroll
        for (int w = 0; w < 8; w++) acc += (double)red[tid][w];
        atomicAdd(&g_acc[b][tid], acc);
    }
}

// ============================================================
// Finalize: 4 warps, one per batch; bins spread across lanes.
// ============================================================
__global__ void finalize_kernel(float* __restrict__ out) {
    int w = threadIdx.x >> 5, lane = threadIdx.x & 31;
    if (w >= BB) return;
    const double* a = g_acc[w];

    double tot = 0.0;
    for (int k = lane; k < 50; k += 32) tot += a[NSCAL + k];
    #pragma unroll
    for (int o = 16; o > 0; o >>= 1) tot += __shfl_down_sync(0xffffffffu, tot, o);
    tot = __shfl_sync(0xffffffffu, tot, 0);
    tot += 1e-8;

    double ent = 0.0;
    for (int k = lane; k < 50; k += 32) {
        double p = a[NSCAL + k] / tot;
        ent -= p * log(p + 1e-8);
    }
    #pragma unroll
    for (int o = 16; o > 0; o >>= 1) ent += __shfl_down_sync(0xffffffffu, ent, o);

    if (lane == 0) {
        double n = a[0];
        double nn = n > 1.0 ? n : 1.0;
        double mu = a[1] / nn;
        double M2 = a[2] - 2.0 * mu * a[1] + mu * mu * n;
        double nm1 = (n - 1.0) > 1.0 ? (n - 1.0) : 1.0;
        double var = M2 / nm1;
        double sigma = sqrt(var) + 1e-8;
        double M3 = a[3] - 3.0 * mu * a[2] + 3.0 * mu * mu * a[1] - mu * mu * mu * n;
        double M4 = a[4] - 4.0 * mu * a[3] + 6.0 * mu * mu * a[2]
                  - 4.0 * mu * mu * mu * a[1] + mu * mu * mu * mu * n;
        double sg3 = sigma * sigma * sigma;
        double skew = (M3 / sg3) / nn;
        double kurt = (M4 / (sg3 * sigma)) / nn - 3.0;
        double valid = (n >= 10.0) ? 1.0 : 0.0;

        float* o = out + w * 25;
        o[0] = (float)(mu * valid);
        o[1] = (float)(sigma * valid);
        o[2] = (float)(skew * valid);
        o[3] = (float)(kurt * valid);
        o[4] = (float)(ent * valid);
        for (int f = 0; f < 8; f++) o[5 + f] = (float)(a[5 + f] / nn);
        for (int k = 0; k < 6; k++) o[13 + k] = (float)(a[13 + k] / nn);
        for (int ax = 0; ax < 3; ax++) {
            double s = a[19 + 3 * ax];
            double ss = s > 1.0 ? s : 1.0;
            double ok = (s >= 4.0) ? 1.0 : 0.0;
            o[19 + 2 * ax]     = (float)((a[20 + 3 * ax] / ss) * ok);
            o[19 + 2 * ax + 1] = (float)((a[21 + 3 * ax] / ss) * ok);
        }
    }
}

extern "C" void kernel_launch(void* const* d_in, const int* in_sizes, int n_in,
                              void* d_out, int out_size) {
    const float* x  = (const float*)d_in[0];
    const float* m  = (const float*)d_in[1];
    const float* gf = (const float*)d_in[2];

    prep_kernel<<<1, 352>>>(gf);

    dim3 grid(WW / TXX, HH / TYV, BB * 4);  // (5, 10, 16) = 800 CTAs
    dim3 blk(TXX, 8);
    fused_kernel<<<grid, blk>>>(x, m);

    finalize_kernel<<<1, 128>>>((float*)d_out);
}